// round 15
// baseline (speedup 1.0000x reference)
#include <cuda_runtime.h>
#include <cuda_bf16.h>
#include <math.h>
#include <stdint.h>

#define B_    2
#define NSEQ  4096
#define H_    4
#define DK    256
#define DV    512
#define DM    1024
#define VD    2048
#define NC    64

// ---------------- static scratch (allocation-free rule) ----------------
__device__ float g_q1[(size_t)B_ * NSEQ * DM];
__device__ float g_k1[(size_t)B_ * NSEQ * DM];
__device__ float g_q [(size_t)B_ * NSEQ * DM];
__device__ float g_k [(size_t)B_ * NSEQ * DM];
__device__ float g_v [(size_t)B_ * NSEQ * VD];
__device__ float g_g [(size_t)B_ * NSEQ * VD];
__device__ float g_o [(size_t)B_ * NSEQ * VD];
__device__ float g_U [(size_t)B_ * H_ * NC * DK * DV];   // Ut layout: [bh][c][e][d]
__device__ float g_S [(size_t)B_ * H_ * NC * DK * DV];   // aliased: Sh | Sl (bf16 each)
__device__ float g_cos[(size_t)NSEQ * 128];
__device__ float g_sin[(size_t)NSEQ * 128];

// bf16-split operands
__device__ __nv_bfloat16 g_xh[(size_t)B_ * NSEQ * DM];
__device__ __nv_bfloat16 g_xl[(size_t)B_ * NSEQ * DM];
__device__ __nv_bfloat16 g_wth[8388608];
__device__ __nv_bfloat16 g_wtl[8388608];
__device__ __nv_bfloat16 g_gh[(size_t)B_ * NSEQ * VD];
__device__ __nv_bfloat16 g_gl[(size_t)B_ * NSEQ * VD];

#define WOFF_Q 0
#define WOFF_K 1048576
#define WOFF_V 2097152
#define WOFF_G 4194304
#define WOFF_O 6291456

#define SELEMS ((size_t)B_ * H_ * NC * DK * DV)   // 67108864 elems

// =====================================================================
//  shared mma helpers
// =====================================================================
__device__ __forceinline__ void mma16816(float* d, const uint32_t* a, const uint32_t* b) {
    asm volatile(
        "mma.sync.aligned.m16n8k16.row.col.f32.bf16.bf16.f32 "
        "{%0,%1,%2,%3}, {%4,%5,%6,%7}, {%8,%9}, {%0,%1,%2,%3};"
        : "+f"(d[0]), "+f"(d[1]), "+f"(d[2]), "+f"(d[3])
        : "r"(a[0]), "r"(a[1]), "r"(a[2]), "r"(a[3]), "r"(b[0]), "r"(b[1]));
}
__device__ __forceinline__ void cpa16(uint32_t dst, const void* src) {
    asm volatile("cp.async.cg.shared.global [%0], [%1], 16;" :: "r"(dst), "l"(src));
}
__device__ __forceinline__ void cpa_commit() {
    asm volatile("cp.async.commit_group;" ::: "memory");
}
template <int N>
__device__ __forceinline__ void cpa_wait() {
    asm volatile("cp.async.wait_group %0;" :: "n"(N) : "memory");
}
__device__ __forceinline__ void split_store(__nv_bfloat16* H, __nv_bfloat16* L, int idx, float v) {
    const __nv_bfloat16 h = __float2bfloat16(v);
    H[idx] = h;
    L[idx] = __float2bfloat16(v - __bfloat162float(h));
}

// =====================================================================
//  warp-MMA GEMM with cp.async 2-stage pipeline (unchanged from R11)
// =====================================================================
#define BM 128
#define BN 128
#define BK 32
#define ASTR 40
#define TILE_E (BM * ASTR)
#define STG_E  (4 * TILE_E)
#define GEMM_DSMEM (2 * STG_E * 2)

template <int EPI>
__global__ __launch_bounds__(256)
void gemm_mma(const __nv_bfloat16* __restrict__ Ah, const __nv_bfloat16* __restrict__ Al,
              const __nv_bfloat16* __restrict__ Bh, const __nv_bfloat16* __restrict__ Bl,
              float* __restrict__ C, int M, int Ncols, int K)
{
    extern __shared__ __nv_bfloat16 dyn[];

    const int tid = threadIdx.x;
    const int wid = tid >> 5, lane = tid & 31;
    const int warp_m = wid & 1;
    const int warp_n = wid >> 1;
    const int bm = blockIdx.y * BM;
    const int bn = blockIdx.x * BN;

    const int lrow = tid >> 1;
    const int lk   = (tid & 1) * 16;
    const int so   = lrow * ASTR + lk;

    const int g  = lane >> 2;
    const int cq = (lane & 3) * 2;

    float acc[4][4][4];
    #pragma unroll
    for (int mt = 0; mt < 4; mt++)
        #pragma unroll
        for (int nt = 0; nt < 4; nt++)
            #pragma unroll
            for (int r = 0; r < 4; r++) acc[mt][nt][r] = 0.0f;

    const int nIter = K / BK;

    auto load_stage = [&](int s, int k0) {
        __nv_bfloat16* st = dyn + s * STG_E;
        const uint32_t sb = (uint32_t)__cvta_generic_to_shared(st);
        const size_t ga = (size_t)(bm + lrow) * K + k0 + lk;
        const size_t gb = (size_t)(bn + lrow) * K + k0 + lk;
        const uint32_t d0 = sb + so * 2;
        cpa16(d0,                        Ah + ga);
        cpa16(d0 + 16,                   Ah + ga + 8);
        cpa16(d0 + TILE_E * 2,           Al + ga);
        cpa16(d0 + TILE_E * 2 + 16,      Al + ga + 8);
        cpa16(d0 + 2 * TILE_E * 2,       Bh + gb);
        cpa16(d0 + 2 * TILE_E * 2 + 16,  Bh + gb + 8);
        cpa16(d0 + 3 * TILE_E * 2,       Bl + gb);
        cpa16(d0 + 3 * TILE_E * 2 + 16,  Bl + gb + 8);
        cpa_commit();
    };

    load_stage(0, 0);

    for (int it = 0; it < nIter; it++) {
        if (it + 1 < nIter) {
            load_stage((it + 1) & 1, (it + 1) * BK);
            cpa_wait<1>();
        } else {
            cpa_wait<0>();
        }
        __syncthreads();

        const __nv_bfloat16* st  = dyn + (it & 1) * STG_E;
        const __nv_bfloat16* sAh = st;
        const __nv_bfloat16* sAl = st + TILE_E;
        const __nv_bfloat16* sBh = st + 2 * TILE_E;
        const __nv_bfloat16* sBl = st + 3 * TILE_E;

        #pragma unroll
        for (int ks = 0; ks < 2; ks++) {
            const int kb = ks * 16;
            uint32_t bh[4][2], bl[4][2];
            #pragma unroll
            for (int nt = 0; nt < 4; nt++) {
                const int nrow = warp_n * 32 + nt * 8 + g;
                const int koff = nrow * ASTR + kb + cq;
                bh[nt][0] = *(const uint32_t*)&sBh[koff];
                bh[nt][1] = *(const uint32_t*)&sBh[koff + 8];
                bl[nt][0] = *(const uint32_t*)&sBl[koff];
                bl[nt][1] = *(const uint32_t*)&sBl[koff + 8];
            }
            #pragma unroll
            for (int mt = 0; mt < 4; mt++) {
                const int ar = warp_m * 64 + mt * 16 + g;
                const int ao = ar * ASTR + kb + cq;
                uint32_t ah[4], al[4];
                ah[0] = *(const uint32_t*)&sAh[ao];
                ah[1] = *(const uint32_t*)&sAh[ao + 8 * ASTR];
                ah[2] = *(const uint32_t*)&sAh[ao + 8];
                ah[3] = *(const uint32_t*)&sAh[ao + 8 * ASTR + 8];
                al[0] = *(const uint32_t*)&sAl[ao];
                al[1] = *(const uint32_t*)&sAl[ao + 8 * ASTR];
                al[2] = *(const uint32_t*)&sAl[ao + 8];
                al[3] = *(const uint32_t*)&sAl[ao + 8 * ASTR + 8];
                #pragma unroll
                for (int nt = 0; nt < 4; nt++) {
                    mma16816(acc[mt][nt], ah, bh[nt]);
                    mma16816(acc[mt][nt], ah, bl[nt]);
                    mma16816(acc[mt][nt], al, bh[nt]);
                }
            }
        }
        __syncthreads();
    }

    #pragma unroll
    for (int mt = 0; mt < 4; mt++) {
        #pragma unroll
        for (int nt = 0; nt < 4; nt++) {
            const int row0 = bm + warp_m * 64 + mt * 16 + g;
            const int col  = bn + warp_n * 32 + nt * 8 + cq;
            #pragma unroll
            for (int half = 0; half < 2; half++) {
                const int row = row0 + half * 8;
                float v0 = acc[mt][nt][half * 2 + 0];
                float v1 = acc[mt][nt][half * 2 + 1];
                if (EPI == 1) {
                    v0 = v0 / (1.0f + expf(-v0));
                    v1 = v1 / (1.0f + expf(-v1));
                }
                if (EPI == 2) {
                    const int bb = row >> 12, nn = row & 4095;
                    const int hh = col >> 9,  ee = col & 511;
                    float2* p = (float2*)(g_v + (((size_t)(bb * H_ + hh)) * NSEQ + nn) * DV + ee);
                    *p = make_float2(v0, v1);
                } else {
                    float2* p = (float2*)(C + (size_t)row * Ncols + col);
                    *p = make_float2(v0, v1);
                }
            }
        }
    }
}

// ---------------- weight transpose + bf16 split ----------------
__global__ void wsplitT(const float* __restrict__ W, __nv_bfloat16* __restrict__ Th,
                        __nv_bfloat16* __restrict__ Tl, int K, int N)
{
    __shared__ float t[32][33];
    const int n0 = blockIdx.x * 32, k0 = blockIdx.y * 32;
    const int tx = threadIdx.x, ty = threadIdx.y;
    #pragma unroll
    for (int i = 0; i < 4; i++)
        t[ty * 4 + i][tx] = W[(size_t)(k0 + ty * 4 + i) * N + n0 + tx];
    __syncthreads();
    #pragma unroll
    for (int i = 0; i < 4; i++) {
        const int r = ty * 4 + i;
        const float v = t[tx][r];
        const __nv_bfloat16 h = __float2bfloat16(v);
        const __nv_bfloat16 l = __float2bfloat16(v - __bfloat162float(h));
        Th[(size_t)(n0 + r) * K + k0 + tx] = h;
        Tl[(size_t)(n0 + r) * K + k0 + tx] = l;
    }
}

// ---------------- row-major bf16 split (activations) ----------------
__global__ void split_rows(const float* __restrict__ A, __nv_bfloat16* __restrict__ H,
                           __nv_bfloat16* __restrict__ L)
{
    const int i = blockIdx.x * blockDim.x + threadIdx.x;
    const float4 v = ((const float4*)A)[i];
    const __nv_bfloat16 h0 = __float2bfloat16(v.x);
    const __nv_bfloat16 h1 = __float2bfloat16(v.y);
    const __nv_bfloat16 h2 = __float2bfloat16(v.z);
    const __nv_bfloat16 h3 = __float2bfloat16(v.w);
    ((__nv_bfloat162*)H)[i * 2 + 0] = __halves2bfloat162(h0, h1);
    ((__nv_bfloat162*)H)[i * 2 + 1] = __halves2bfloat162(h2, h3);
    const __nv_bfloat16 l0 = __float2bfloat16(v.x - __bfloat162float(h0));
    const __nv_bfloat16 l1 = __float2bfloat16(v.y - __bfloat162float(h1));
    const __nv_bfloat16 l2 = __float2bfloat16(v.z - __bfloat162float(h2));
    const __nv_bfloat16 l3 = __float2bfloat16(v.w - __bfloat162float(h3));
    ((__nv_bfloat162*)L)[i * 2 + 0] = __halves2bfloat162(l0, l1);
    ((__nv_bfloat162*)L)[i * 2 + 1] = __halves2bfloat162(l2, l3);
}

// ---------------- rotary table ----------------
__global__ void rope_table(float* __restrict__ cosT, float* __restrict__ sinT)
{
    const int t = blockIdx.x;
    const int i = threadIdx.x;
    const double m = (double)i * (1.0 / 128.0);
    const double invf = exp(-m * 9.210340371976184);
    const float pf = (float)t * (float)invf;
    const double ph = (double)pf;
    const double kq = rint(ph * 0.15915494309189535);
    const float rf = (float)(ph - kq * 6.283185307179586);
    cosT[t * 128 + i] = cosf(rf);
    sinT[t * 128 + i] = sinf(rf);
}

// ---------------- rotary + transpose to (B,H,N,dk), q scaled ----------------
__global__ void rope_apply(const float* __restrict__ Q1, const float* __restrict__ K1,
                           float* __restrict__ Qo, float* __restrict__ Ko,
                           const float* __restrict__ cosT, const float* __restrict__ sinT)
{
    const int idx = blockIdx.x * blockDim.x + threadIdx.x;
    const int i  = idx & 127;
    const int hh = (idx >> 7) & 3;
    const int n  = (idx >> 9) & 4095;
    const int b  = idx >> 21;
    const float cv = cosT[n * 128 + i];
    const float sv = sinT[n * 128 + i];
    const size_t src = ((size_t)(b * NSEQ + n)) * DM + hh * DK + i;
    const size_t dst = (((size_t)(b * H_ + hh)) * NSEQ + n) * DK + i;

    const float qa = Q1[src], qb = Q1[src + 128];
    Qo[dst]       = (qa * cv - qb * sv) * 0.0625f;
    Qo[dst + 128] = (qb * cv + qa * sv) * 0.0625f;
    const float ka = K1[src], kb = K1[src + 128];
    Ko[dst]       = ka * cv - kb * sv;
    Ko[dst + 128] = kb * cv + ka * sv;
}

// =====================================================================
//  phase A (mma): Ut[e][d] = sum_j V[j][e] * (K[j][d] * gamma^(63-j))
//  block: z chunk, e-block 128 (x), d-block 128 (y). 256 threads.
// =====================================================================
#define RSTR 72
#define CKV_DSMEM (4 * 128 * RSTR * 2)   // vTh, vTl, kTh, kTl

__global__ __launch_bounds__(256)
void chunk_kv_mma(const float* __restrict__ K, const float* __restrict__ V,
                  float* __restrict__ U)
{
    extern __shared__ __nv_bfloat16 sm[];
    __nv_bfloat16* vTh = sm;
    __nv_bfloat16* vTl = sm + 128 * RSTR;
    __nv_bfloat16* kTh = sm + 2 * 128 * RSTR;
    __nv_bfloat16* kTl = sm + 3 * 128 * RSTR;
    __shared__ float gj[64];

    const int tid = threadIdx.x;
    const int wid = tid >> 5, lane = tid & 31;
    const int g = lane >> 2, cq = (lane & 3) * 2;
    const int warp_m = wid & 1;      // e: 2 x 64
    const int warp_n = wid >> 1;     // d: 4 x 32

    const int z = blockIdx.z;
    const int bh = z >> 6, c = z & 63;
    const int hd = bh & 3;
    const int e0 = blockIdx.x * 128;
    const int d0 = blockIdx.y * 128;
    const float gamma = 1.0f - exp2f(-(float)(5 + hd));
    if (tid < 64) gj[tid] = powf(gamma, (float)(63 - tid));
    __syncthreads();

    const float* kptr = K + ((size_t)bh * NSEQ + c * 64) * DK;
    const float* vptr = V + ((size_t)bh * NSEQ + c * 64) * DV;

    // transposed loads: j = tid>>2, 32 cols each
    {
        const int j = tid >> 2;
        const int c0 = (tid & 3) * 32;
        const float sk = gj[j];
        #pragma unroll
        for (int u = 0; u < 8; u++) {
            float4 vv = *(const float4*)(vptr + (size_t)j * DV + e0 + c0 + u * 4);
            const float va[4] = {vv.x, vv.y, vv.z, vv.w};
            #pragma unroll
            for (int x = 0; x < 4; x++)
                split_store(vTh, vTl, (c0 + u * 4 + x) * RSTR + j, va[x]);
            float4 kk = *(const float4*)(kptr + (size_t)j * DK + d0 + c0 + u * 4);
            const float ka[4] = {kk.x * sk, kk.y * sk, kk.z * sk, kk.w * sk};
            #pragma unroll
            for (int x = 0; x < 4; x++)
                split_store(kTh, kTl, (c0 + u * 4 + x) * RSTR + j, ka[x]);
        }
    }
    __syncthreads();

    float acc[4][4][4];
    #pragma unroll
    for (int mt = 0; mt < 4; mt++)
        #pragma unroll
        for (int nt = 0; nt < 4; nt++)
            #pragma unroll
            for (int r = 0; r < 4; r++) acc[mt][nt][r] = 0.0f;

    #pragma unroll
    for (int ks = 0; ks < 4; ks++) {
        const int kb = ks * 16;
        uint32_t bh_[4][2], bl_[4][2];
        #pragma unroll
        for (int nt = 0; nt < 4; nt++) {
            const int nrow = warp_n * 32 + nt * 8 + g;
            const int ko = nrow * RSTR + kb + cq;
            bh_[nt][0] = *(const uint32_t*)&kTh[ko];
            bh_[nt][1] = *(const uint32_t*)&kTh[ko + 8];
            bl_[nt][0] = *(const uint32_t*)&kTl[ko];
            bl_[nt][1] = *(const uint32_t*)&kTl[ko + 8];
        }
        #pragma unroll
        for (int mt = 0; mt < 4; mt++) {
            const int mrow = warp_m * 64 + mt * 16 + g;
            const int ao = mrow * RSTR + kb + cq;
            uint32_t ah[4], al[4];
            ah[0] = *(const uint32_t*)&vTh[ao];
            ah[1] = *(const uint32_t*)&vTh[ao + 8 * RSTR];
            ah[2] = *(const uint32_t*)&vTh[ao + 8];
            ah[3] = *(const uint32_t*)&vTh[ao + 8 * RSTR + 8];
            al[0] = *(const uint32_t*)&vTl[ao];
            al[1] = *(const uint32_t*)&vTl[ao + 8 * RSTR];
            al[2] = *(const uint32_t*)&vTl[ao + 8];
            al[3] = *(const uint32_t*)&vTl[ao + 8 * RSTR + 8];
            #pragma unroll
            for (int nt = 0; nt < 4; nt++) {
                mma16816(acc[mt][nt], ah, bh_[nt]);
                mma16816(acc[mt][nt], ah, bl_[nt]);
                mma16816(acc[mt][nt], al, bh_[nt]);
            }
        }
    }

    float* uptr = U + (size_t)z * DK * DV;
    #pragma unroll
    for (int mt = 0; mt < 4; mt++) {
        #pragma unroll
        for (int nt = 0; nt < 4; nt++) {
            const int e = e0 + warp_m * 64 + mt * 16 + g;
            const int d = d0 + warp_n * 32 + nt * 8 + cq;
            #pragma unroll
            for (int half = 0; half < 2; half++) {
                float2* p = (float2*)(uptr + (size_t)(e + half * 8) * DK + d);
                *p = make_float2(acc[mt][nt][half * 2], acc[mt][nt][half * 2 + 1]);
            }
        }
    }
}

// ---------------- phase B: decay scan, emits S as bf16 hi/lo ----------------
__global__ void scan_state(const float* __restrict__ U,
                           __nv_bfloat16* __restrict__ Sh, __nv_bfloat16* __restrict__ Sl)
{
    const int idx = blockIdx.x * blockDim.x + threadIdx.x;   // 8*512*128
    const int d2 = (idx & 127) * 2;
    const int e  = (idx >> 7) & 511;
    const int bh = idx >> 16;
    const int hd = bh & 3;
    const float gamma = 1.0f - exp2f(-(float)(5 + hd));
    const float gC = powf(gamma, 64.0f);
    const size_t base = ((size_t)bh * 64) * (DK * DV) + (size_t)e * DK + d2;
    float s0 = 0.0f, s1 = 0.0f;
    for (int c = 0; c < 64; c++) {
        const size_t off = base + (size_t)c * (DK * DV);
        const __nv_bfloat16 h0 = __float2bfloat16(s0);
        const __nv_bfloat16 h1 = __float2bfloat16(s1);
        *(__nv_bfloat162*)(Sh + off) = __halves2bfloat162(h0, h1);
        *(__nv_bfloat162*)(Sl + off) = __halves2bfloat162(
            __float2bfloat16(s0 - __bfloat162float(h0)),
            __float2bfloat16(s1 - __bfloat162float(h1)));
        const float2 u = *(const float2*)(U + off);
        s0 = gC * s0 + u.x;
        s1 = gC * s1 + u.y;
    }
}

// =====================================================================
//  phase C (mma): o = mask(q k^T) V + (q * gamma^(i+1)) S
//  block: z chunk (y), e-block 128 (x). 256 threads (8 warps).
// =====================================================================
#define RET_BUFA 27648                      // elems: phase buffers
#define RET_DSMEM ((RET_BUFA + 2 * 4608) * 2)

__global__ __launch_bounds__(256)
void retention_mma(const float* __restrict__ Q, const float* __restrict__ Kp,
                   const float* __restrict__ V,
                   const __nv_bfloat16* __restrict__ Sh, const __nv_bfloat16* __restrict__ Sl,
                   float* __restrict__ O)
{
    extern __shared__ __nv_bfloat16 sm[];
    __nv_bfloat16* bufA  = sm;
    __nv_bfloat16* attnh = sm + RET_BUFA;
    __nv_bfloat16* attnl = sm + RET_BUFA + 4608;
    __shared__ float gpow[72];

    const int tid = threadIdx.x;
    const int wid = tid >> 5, lane = tid & 31;
    const int g = lane >> 2, cq = (lane & 3) * 2;

    const int z = blockIdx.y;
    const int bh = z >> 6, c = z & 63;
    const int hd = bh & 3, b = bh >> 2;
    const int e0 = blockIdx.x * 128;
    const float gamma = 1.0f - exp2f(-(float)(5 + hd));
    if (tid < 66) gpow[tid] = powf(gamma, (float)tid);
    __syncthreads();

    const float* qptr = Q + ((size_t)bh * NSEQ + c * 64) * DK;
    const float* kptr = Kp + ((size_t)bh * NSEQ + c * 64) * DK;
    const float* vptr = V + ((size_t)bh * NSEQ + c * 64) * DV;
    const size_t soff = (size_t)z * DK * DV;

    // ---------------- phase 1: attn = q k^T (m64 n64 k256) ----------------
    const int w_i = wid & 1;     // 2 x 32 rows
    const int w_j = wid >> 1;    // 4 x 16 cols
    float acc_a[2][2][4];
    #pragma unroll
    for (int mt = 0; mt < 2; mt++)
        #pragma unroll
        for (int nt = 0; nt < 2; nt++)
            #pragma unroll
            for (int r = 0; r < 4; r++) acc_a[mt][nt][r] = 0.0f;

    __nv_bfloat16* qh = bufA;
    __nv_bfloat16* ql = bufA + 4608;
    __nv_bfloat16* kh = bufA + 9216;
    __nv_bfloat16* kl = bufA + 13824;

    const int lrow = tid >> 2;          // 0..63
    const int lc0  = (tid & 3) * 16;

    for (int dc = 0; dc < 4; dc++) {
        const int dbase = dc * 64;
        #pragma unroll
        for (int u = 0; u < 4; u++) {
            float4 qv = *(const float4*)(qptr + (size_t)lrow * DK + dbase + lc0 + u * 4);
            const float qa[4] = {qv.x, qv.y, qv.z, qv.w};
            #pragma unroll
            for (int x = 0; x < 4; x++)
                split_store(qh, ql, lrow * RSTR + lc0 + u * 4 + x, qa[x]);
            float4 kv = *(const float4*)(kptr + (size_t)lrow * DK + dbase + lc0 + u * 4);
            const float ka[4] = {kv.x, kv.y, kv.z, kv.w};
            #pragma unroll
            for (int x = 0; x < 4; x++)
                split_store(kh, kl, lrow * RSTR + lc0 + u * 4 + x, ka[x]);
        }
        __syncthreads();

        #pragma unroll
        for (int ks = 0; ks < 4; ks++) {
            const int kb = ks * 16;
            uint32_t bh_[2][2], bl_[2][2];
            #pragma unroll
            for (int nt = 0; nt < 2; nt++) {
                const int nrow = w_j * 16 + nt * 8 + g;
                const int ko = nrow * RSTR + kb + cq;
                bh_[nt][0] = *(const uint32_t*)&kh[ko];
                bh_[nt][1] = *(const uint32_t*)&kh[ko + 8];
                bl_[nt][0] = *(const uint32_t*)&kl[ko];
                bl_[nt][1] = *(const uint32_t*)&kl[ko + 8];
            }
            #pragma unroll
            for (int mt = 0; mt < 2; mt++) {
                const int mrow = w_i * 32 + mt * 16 + g;
                const int ao = mrow * RSTR + kb + cq;
                uint32_t ah[4], al[4];
                ah[0] = *(const uint32_t*)&qh[ao];
                ah[1] = *(const uint32_t*)&qh[ao + 8 * RSTR];
                ah[2] = *(const uint32_t*)&qh[ao + 8];
                ah[3] = *(const uint32_t*)&qh[ao + 8 * RSTR + 8];
                al[0] = *(const uint32_t*)&ql[ao];
                al[1] = *(const uint32_t*)&ql[ao + 8 * RSTR];
                al[2] = *(const uint32_t*)&ql[ao + 8];
                al[3] = *(const uint32_t*)&ql[ao + 8 * RSTR + 8];
                #pragma unroll
                for (int nt = 0; nt < 2; nt++) {
                    mma16816(acc_a[mt][nt], ah, bh_[nt]);
                    mma16816(acc_a[mt][nt], ah, bl_[nt]);
                    mma16816(acc_a[mt][nt], al, bh_[nt]);
                }
            }
        }
        __syncthreads();
    }

    // mask + decay, store attn as bf16 split
    #pragma unroll
    for (int mt = 0; mt < 2; mt++)
        #pragma unroll
        for (int nt = 0; nt < 2; nt++)
            #pragma unroll
            for (int half = 0; half < 2; half++) {
                const int i = w_i * 32 + mt * 16 + g + half * 8;
                #pragma unroll
                for (int x = 0; x < 2; x++) {
                    const int j = w_j * 16 + nt * 8 + cq + x;
                    const float v = (i >= j) ? acc_a[mt][nt][half * 2 + x] * gpow[i - j] : 0.0f;
                    split_store(attnh, attnl, i * RSTR + j, v);
                }
            }
    __syncthreads();

    // ---------------- phase 2: o += attn @ V (m64 n128 k64) ----------------
    const int w_i2 = wid & 1;     // 2 x 32 rows
    const int w_e  = wid >> 1;    // 4 x 32 cols
    float acc_o[2][4][4];
    #pragma unroll
    for (int mt = 0; mt < 2; mt++)
        #pragma unroll
        for (int nt = 0; nt < 4; nt++)
            #pragma unroll
            for (int r = 0; r < 4; r++) acc_o[mt][nt][r] = 0.0f;

    __nv_bfloat16* vTh = bufA;
    __nv_bfloat16* vTl = bufA + 9216;
    {
        const int j = tid >> 2;
        const int c0 = (tid & 3) * 32;
        #pragma unroll
        for (int u = 0; u < 8; u++) {
            float4 vv = *(const float4*)(vptr + (size_t)j * DV + e0 + c0 + u * 4);
            const float va[4] = {vv.x, vv.y, vv.z, vv.w};
            #pragma unroll
            for (int x = 0; x < 4; x++)
                split_store(vTh, vTl, (c0 + u * 4 + x) * RSTR + j, va[x]);
        }
    }
    __syncthreads();

    #pragma unroll
    for (int ks = 0; ks < 4; ks++) {
        const int kb = ks * 16;
        uint32_t bh_[4][2], bl_[4][2];
        #pragma unroll
        for (int nt = 0; nt < 4; nt++) {
            const int nrow = w_e * 32 + nt * 8 + g;
            const int ko = nrow * RSTR + kb + cq;
            bh_[nt][0] = *(const uint32_t*)&vTh[ko];
            bh_[nt][1] = *(const uint32_t*)&vTh[ko + 8];
            bl_[nt][0] = *(const uint32_t*)&vTl[ko];
            bl_[nt][1] = *(const uint32_t*)&vTl[ko + 8];
        }
        #pragma unroll
        for (int mt = 0; mt < 2; mt++) {
            const int mrow = w_i2 * 32 + mt * 16 + g;
            const int ao = mrow * RSTR + kb + cq;
            uint32_t ah[4], al[4];
            ah[0] = *(const uint32_t*)&attnh[ao];
            ah[1] = *(const uint32_t*)&attnh[ao + 8 * RSTR];
            ah[2] = *(const uint32_t*)&attnh[ao + 8];
            ah[3] = *(const uint32_t*)&attnh[ao + 8 * RSTR + 8];
            al[0] = *(const uint32_t*)&attnl[ao];
            al[1] = *(const uint32_t*)&attnl[ao + 8 * RSTR];
            al[2] = *(const uint32_t*)&attnl[ao + 8];
            al[3] = *(const uint32_t*)&attnl[ao + 8 * RSTR + 8];
            #pragma unroll
            for (int nt = 0; nt < 4; nt++) {
                mma16816(acc_o[mt][nt], ah, bh_[nt]);
                mma16816(acc_o[mt][nt], ah, bl_[nt]);
                mma16816(acc_o[mt][nt], al, bh_[nt]);
            }
        }
    }
    __syncthreads();

    // ---------------- phase 3: o += (q * gamma^(i+1)) @ S (m64 n128 k256) ----------------
    __nv_bfloat16* qch = bufA;
    __nv_bfloat16* qcl = bufA + 4608;
    __nv_bfloat16* sth = bufA + 9216;
    __nv_bfloat16* stl = bufA + 18432;

    for (int dc = 0; dc < 4; dc++) {
        const int dbase = dc * 64;
        // qc load (row = i)
        {
            const float sc = gpow[lrow + 1];
            #pragma unroll
            for (int u = 0; u < 4; u++) {
                float4 qv = *(const float4*)(qptr + (size_t)lrow * DK + dbase + lc0 + u * 4);
                const float qa[4] = {qv.x * sc, qv.y * sc, qv.z * sc, qv.w * sc};
                #pragma unroll
                for (int x = 0; x < 4; x++)
                    split_store(qch, qcl, lrow * RSTR + lc0 + u * 4 + x, qa[x]);
            }
        }
        // St tiles: rows e (128), cols d (64), natural layout — direct uint4 copies
        {
            const int e = tid >> 1;
            const int c0 = (tid & 1) * 32;
            const size_t gsrc = soff + (size_t)(e0 + e) * DK + dbase + c0;
            #pragma unroll
            for (int u = 0; u < 4; u++) {
                *(uint4*)&sth[e * RSTR + c0 + u * 8] = *(const uint4*)(Sh + gsrc + u * 8);
                *(uint4*)&stl[e * RSTR + c0 + u * 8] = *(const uint4*)(Sl + gsrc + u * 8);
            }
        }
        __syncthreads();

        #pragma unroll
        for (int ks = 0; ks < 4; ks++) {
            const int kb = ks * 16;
            uint32_t bh_[4][2], bl_[4][2];
            #pragma unroll
            for (int nt = 0; nt < 4; nt++) {
                const int nrow = w_e * 32 + nt * 8 + g;
                const int ko = nrow * RSTR + kb + cq;
                bh_[nt][0] = *(const uint32_t*)&sth[ko];
                bh_[nt][1] = *(const uint32_t*)&sth[ko + 8];
                bl_[nt][0] = *(const uint32_t*)&stl[ko];
                bl_[nt][1] = *(const uint32_t*)&stl[ko + 8];
            }
            #pragma unroll
            for (int mt = 0; mt < 2; mt++) {
                const int mrow = w_i2 * 32 + mt * 16 + g;
                const int ao = mrow * RSTR + kb + cq;
                uint32_t ah[4], al[4];
                ah[0] = *(const uint32_t*)&qch[ao];
                ah[1] = *(const uint32_t*)&qch[ao + 8 * RSTR];
                ah[2] = *(const uint32_t*)&qch[ao + 8];
                ah[3] = *(const uint32_t*)&qch[ao + 8 * RSTR + 8];
                al[0] = *(const uint32_t*)&qcl[ao];
                al[1] = *(const uint32_t*)&qcl[ao + 8 * RSTR];
                al[2] = *(const uint32_t*)&qcl[ao + 8];
                al[3] = *(const uint32_t*)&qcl[ao + 8 * RSTR + 8];
                #pragma unroll
                for (int nt = 0; nt < 4; nt++) {
                    mma16816(acc_o[mt][nt], ah, bh_[nt]);
                    mma16816(acc_o[mt][nt], ah, bl_[nt]);
                    mma16816(acc_o[mt][nt], al, bh_[nt]);
                }
            }
        }
        __syncthreads();
    }

    // epilogue: O in (B,N,H,dv)
    #pragma unroll
    for (int mt = 0; mt < 2; mt++)
        #pragma unroll
        for (int nt = 0; nt < 4; nt++)
            #pragma unroll
            for (int half = 0; half < 2; half++) {
                const int i = w_i2 * 32 + mt * 16 + g + half * 8;
                const int e = e0 + w_e * 32 + nt * 8 + cq;
                float2* p = (float2*)(O + (((size_t)(b * NSEQ + c * 64 + i)) * H_ + hd) * DV + e);
                *p = make_float2(acc_o[mt][nt][half * 2], acc_o[mt][nt][half * 2 + 1]);
            }
}

// ---------------- rmsnorm * silu-gate -> bf16 hi/lo for Wo GEMM ----------------
__global__ void norm_gate(const float* __restrict__ O, const float* __restrict__ G,
                          const float* __restrict__ w,
                          __nv_bfloat16* __restrict__ Gh, __nv_bfloat16* __restrict__ Gl)
{
    __shared__ float red[4];
    const int row = blockIdx.x;
    const int tid = threadIdx.x;
    const size_t base = (size_t)row * DV;

    float4 x = *(const float4*)(O + base + tid * 4);
    float ss = x.x * x.x + x.y * x.y + x.z * x.z + x.w * x.w;
    #pragma unroll
    for (int off = 16; off; off >>= 1) ss += __shfl_xor_sync(0xffffffff, ss, off);
    if ((tid & 31) == 0) red[tid >> 5] = ss;
    __syncthreads();
    const float tot = red[0] + red[1] + red[2] + red[3];
    const float inv = rsqrtf(tot * (1.0f / (float)DV) + 1e-5f);

    float4 wv = *(const float4*)(w + tid * 4);
    float4 gv = *(const float4*)(G + base + tid * 4);
    float o0 = x.x * inv * wv.x * gv.x;
    float o1 = x.y * inv * wv.y * gv.y;
    float o2 = x.z * inv * wv.z * gv.z;
    float o3 = x.w * inv * wv.w * gv.w;

    const __nv_bfloat16 h0 = __float2bfloat16(o0);
    const __nv_bfloat16 h1 = __float2bfloat16(o1);
    const __nv_bfloat16 h2 = __float2bfloat16(o2);
    const __nv_bfloat16 h3 = __float2bfloat16(o3);
    const size_t p = (base >> 1) + tid * 2;
    ((__nv_bfloat162*)Gh)[p + 0] = __halves2bfloat162(h0, h1);
    ((__nv_bfloat162*)Gh)[p + 1] = __halves2bfloat162(h2, h3);
    ((__nv_bfloat162*)Gl)[p + 0] = __halves2bfloat162(
        __float2bfloat16(o0 - __bfloat162float(h0)), __float2bfloat16(o1 - __bfloat162float(h1)));
    ((__nv_bfloat162*)Gl)[p + 1] = __halves2bfloat162(
        __float2bfloat16(o2 - __bfloat162float(h2)), __float2bfloat16(o3 - __bfloat162float(h3)));
}

// ---------------- launch ----------------
extern "C" void kernel_launch(void* const* d_in, const int* in_sizes, int n_in,
                              void* d_out, int out_size)
{
    const float* x  = (const float*)d_in[0];
    const float* Wq = (const float*)d_in[1];
    const float* Wk = (const float*)d_in[2];
    const float* Wv = (const float*)d_in[3];
    const float* Wg = (const float*)d_in[4];
    const float* Wo = (const float*)d_in[5];
    const float* gw = (const float*)d_in[6];
    float* out = (float*)d_out;

    float *q1, *k1, *q, *k, *v, *g, *o, *U, *S, *ct, *st;
    __nv_bfloat16 *xh, *xl, *wth, *wtl, *gh, *gl;
    cudaGetSymbolAddress((void**)&q1, g_q1);
    cudaGetSymbolAddress((void**)&k1, g_k1);
    cudaGetSymbolAddress((void**)&q,  g_q);
    cudaGetSymbolAddress((void**)&k,  g_k);
    cudaGetSymbolAddress((void**)&v,  g_v);
    cudaGetSymbolAddress((void**)&g,  g_g);
    cudaGetSymbolAddress((void**)&o,  g_o);
    cudaGetSymbolAddress((void**)&U,  g_U);
    cudaGetSymbolAddress((void**)&S,  g_S);
    cudaGetSymbolAddress((void**)&ct, g_cos);
    cudaGetSymbolAddress((void**)&st, g_sin);
    cudaGetSymbolAddress((void**)&xh, g_xh);
    cudaGetSymbolAddress((void**)&xl, g_xl);
    cudaGetSymbolAddress((void**)&wth, g_wth);
    cudaGetSymbolAddress((void**)&wtl, g_wtl);
    cudaGetSymbolAddress((void**)&gh, g_gh);
    cudaGetSymbolAddress((void**)&gl, g_gl);

    __nv_bfloat16* Sh = (__nv_bfloat16*)S;
    __nv_bfloat16* Sl = Sh + SELEMS;

    cudaFuncSetAttribute(gemm_mma<0>, cudaFuncAttributeMaxDynamicSharedMemorySize, GEMM_DSMEM);
    cudaFuncSetAttribute(gemm_mma<1>, cudaFuncAttributeMaxDynamicSharedMemorySize, GEMM_DSMEM);
    cudaFuncSetAttribute(gemm_mma<2>, cudaFuncAttributeMaxDynamicSharedMemorySize, GEMM_DSMEM);
    cudaFuncSetAttribute(chunk_kv_mma, cudaFuncAttributeMaxDynamicSharedMemorySize, CKV_DSMEM);
    cudaFuncSetAttribute(retention_mma, cudaFuncAttributeMaxDynamicSharedMemorySize, RET_DSMEM);

    const int M = B_ * NSEQ;  // 8192

    // bf16 splits: activations + transposed weights
    split_rows<<<(M * DM / 4) / 256, 256>>>(x, xh, xl);
    wsplitT<<<dim3(DM / 32, DM / 32), dim3(32, 8)>>>(Wq, wth + WOFF_Q, wtl + WOFF_Q, DM, DM);
    wsplitT<<<dim3(DM / 32, DM / 32), dim3(32, 8)>>>(Wk, wth + WOFF_K, wtl + WOFF_K, DM, DM);
    wsplitT<<<dim3(VD / 32, DM / 32), dim3(32, 8)>>>(Wv, wth + WOFF_V, wtl + WOFF_V, DM, VD);
    wsplitT<<<dim3(VD / 32, DM / 32), dim3(32, 8)>>>(Wg, wth + WOFF_G, wtl + WOFF_G, DM, VD);
    wsplitT<<<dim3(DM / 32, VD / 32), dim3(32, 8)>>>(Wo, wth + WOFF_O, wtl + WOFF_O, VD, DM);

    // tensor-pipe projections
    gemm_mma<0><<<dim3(DM / BN, M / BM), 256, GEMM_DSMEM>>>(xh, xl, wth + WOFF_Q, wtl + WOFF_Q, q1, M, DM, DM);
    gemm_mma<0><<<dim3(DM / BN, M / BM), 256, GEMM_DSMEM>>>(xh, xl, wth + WOFF_K, wtl + WOFF_K, k1, M, DM, DM);
    gemm_mma<2><<<dim3(VD / BN, M / BM), 256, GEMM_DSMEM>>>(xh, xl, wth + WOFF_V, wtl + WOFF_V, v, M, VD, DM);
    gemm_mma<1><<<dim3(VD / BN, M / BM), 256, GEMM_DSMEM>>>(xh, xl, wth + WOFF_G, wtl + WOFF_G, g, M, VD, DM);

    // rotary
    rope_table<<<NSEQ, 128>>>(ct, st);
    rope_apply<<<(B_ * NSEQ * H_ * 128) / 256, 256>>>(q1, k1, q, k, ct, st);

    // retention on tensor pipe
    chunk_kv_mma<<<dim3(DV / 128, DK / 128, B_ * H_ * NC), 256, CKV_DSMEM>>>(k, v, U);
    scan_state<<<(B_ * H_ * DV * (DK / 2)) / 256, 256>>>(U, Sh, Sl);
    retention_mma<<<dim3(DV / 128, B_ * H_ * NC), 256, RET_DSMEM>>>(q, k, v, Sh, Sl, o);

    // rmsnorm + gate, then output projection
    norm_gate<<<B_ * NSEQ * H_, 128>>>(o, g, gw, gh, gl);
    gemm_mma<0><<<dim3(DM / BN, M / BM), 256, GEMM_DSMEM>>>(gh, gl, wth + WOFF_O, wtl + WOFF_O, out, M, DM, VD);
}

// round 16
// speedup vs baseline: 1.0007x; 1.0007x over previous
#include <cuda_runtime.h>
#include <cuda_bf16.h>
#include <math.h>
#include <stdint.h>

#define B_    2
#define NSEQ  4096
#define H_    4
#define DK    256
#define DV    512
#define DM    1024
#define VD    2048
#define NC    64

// ---------------- static scratch (allocation-free rule) ----------------
__device__ float g_q1[(size_t)B_ * NSEQ * DM];
__device__ float g_k1[(size_t)B_ * NSEQ * DM];
__device__ float g_q [(size_t)B_ * NSEQ * DM];
__device__ float g_k [(size_t)B_ * NSEQ * DM];
__device__ float g_v [(size_t)B_ * NSEQ * VD];
__device__ float g_g [(size_t)B_ * NSEQ * VD];
__device__ float g_o [(size_t)B_ * NSEQ * VD];
__device__ float g_U [(size_t)B_ * H_ * NC * DK * DV];   // Ut layout: [bh][c][e][d]
__device__ float g_S [(size_t)B_ * H_ * NC * DK * DV];   // aliased: Sh | Sl (bf16 each)
__device__ float g_cos[(size_t)NSEQ * 128];
__device__ float g_sin[(size_t)NSEQ * 128];

// bf16-split operands
__device__ __nv_bfloat16 g_xh[(size_t)B_ * NSEQ * DM];
__device__ __nv_bfloat16 g_xl[(size_t)B_ * NSEQ * DM];
__device__ __nv_bfloat16 g_wth[8388608];
__device__ __nv_bfloat16 g_wtl[8388608];
__device__ __nv_bfloat16 g_gh[(size_t)B_ * NSEQ * VD];
__device__ __nv_bfloat16 g_gl[(size_t)B_ * NSEQ * VD];

#define WOFF_Q 0
#define WOFF_K 1048576
#define WOFF_V 2097152
#define WOFF_G 4194304
#define WOFF_O 6291456

#define SELEMS ((size_t)B_ * H_ * NC * DK * DV)   // 67108864 elems

// =====================================================================
//  shared mma helpers
// =====================================================================
__device__ __forceinline__ void mma16816(float* d, const uint32_t* a, const uint32_t* b) {
    asm volatile(
        "mma.sync.aligned.m16n8k16.row.col.f32.bf16.bf16.f32 "
        "{%0,%1,%2,%3}, {%4,%5,%6,%7}, {%8,%9}, {%0,%1,%2,%3};"
        : "+f"(d[0]), "+f"(d[1]), "+f"(d[2]), "+f"(d[3])
        : "r"(a[0]), "r"(a[1]), "r"(a[2]), "r"(a[3]), "r"(b[0]), "r"(b[1]));
}
__device__ __forceinline__ void cpa16(uint32_t dst, const void* src) {
    asm volatile("cp.async.cg.shared.global [%0], [%1], 16;" :: "r"(dst), "l"(src));
}
__device__ __forceinline__ void cpa_commit() {
    asm volatile("cp.async.commit_group;" ::: "memory");
}
template <int N>
__device__ __forceinline__ void cpa_wait() {
    asm volatile("cp.async.wait_group %0;" :: "n"(N) : "memory");
}
__device__ __forceinline__ void split_store(__nv_bfloat16* H, __nv_bfloat16* L, int idx, float v) {
    const __nv_bfloat16 h = __float2bfloat16(v);
    H[idx] = h;
    L[idx] = __float2bfloat16(v - __bfloat162float(h));
}

// =====================================================================
//  warp-MMA GEMM with cp.async 2-stage pipeline (unchanged from R11)
// =====================================================================
#define BM 128
#define BN 128
#define BK 32
#define ASTR 40
#define TILE_E (BM * ASTR)
#define STG_E  (4 * TILE_E)
#define GEMM_DSMEM (2 * STG_E * 2)

template <int EPI>
__global__ __launch_bounds__(256)
void gemm_mma(const __nv_bfloat16* __restrict__ Ah, const __nv_bfloat16* __restrict__ Al,
              const __nv_bfloat16* __restrict__ Bh, const __nv_bfloat16* __restrict__ Bl,
              float* __restrict__ C, int M, int Ncols, int K)
{
    extern __shared__ __nv_bfloat16 dyn[];

    const int tid = threadIdx.x;
    const int wid = tid >> 5, lane = tid & 31;
    const int warp_m = wid & 1;
    const int warp_n = wid >> 1;
    const int bm = blockIdx.y * BM;
    const int bn = blockIdx.x * BN;

    const int lrow = tid >> 1;
    const int lk   = (tid & 1) * 16;
    const int so   = lrow * ASTR + lk;

    const int g  = lane >> 2;
    const int cq = (lane & 3) * 2;

    float acc[4][4][4];
    #pragma unroll
    for (int mt = 0; mt < 4; mt++)
        #pragma unroll
        for (int nt = 0; nt < 4; nt++)
            #pragma unroll
            for (int r = 0; r < 4; r++) acc[mt][nt][r] = 0.0f;

    const int nIter = K / BK;

    auto load_stage = [&](int s, int k0) {
        __nv_bfloat16* st = dyn + s * STG_E;
        const uint32_t sb = (uint32_t)__cvta_generic_to_shared(st);
        const size_t ga = (size_t)(bm + lrow) * K + k0 + lk;
        const size_t gb = (size_t)(bn + lrow) * K + k0 + lk;
        const uint32_t d0 = sb + so * 2;
        cpa16(d0,                        Ah + ga);
        cpa16(d0 + 16,                   Ah + ga + 8);
        cpa16(d0 + TILE_E * 2,           Al + ga);
        cpa16(d0 + TILE_E * 2 + 16,      Al + ga + 8);
        cpa16(d0 + 2 * TILE_E * 2,       Bh + gb);
        cpa16(d0 + 2 * TILE_E * 2 + 16,  Bh + gb + 8);
        cpa16(d0 + 3 * TILE_E * 2,       Bl + gb);
        cpa16(d0 + 3 * TILE_E * 2 + 16,  Bl + gb + 8);
        cpa_commit();
    };

    load_stage(0, 0);

    for (int it = 0; it < nIter; it++) {
        if (it + 1 < nIter) {
            load_stage((it + 1) & 1, (it + 1) * BK);
            cpa_wait<1>();
        } else {
            cpa_wait<0>();
        }
        __syncthreads();

        const __nv_bfloat16* st  = dyn + (it & 1) * STG_E;
        const __nv_bfloat16* sAh = st;
        const __nv_bfloat16* sAl = st + TILE_E;
        const __nv_bfloat16* sBh = st + 2 * TILE_E;
        const __nv_bfloat16* sBl = st + 3 * TILE_E;

        #pragma unroll
        for (int ks = 0; ks < 2; ks++) {
            const int kb = ks * 16;
            uint32_t bh[4][2], bl[4][2];
            #pragma unroll
            for (int nt = 0; nt < 4; nt++) {
                const int nrow = warp_n * 32 + nt * 8 + g;
                const int koff = nrow * ASTR + kb + cq;
                bh[nt][0] = *(const uint32_t*)&sBh[koff];
                bh[nt][1] = *(const uint32_t*)&sBh[koff + 8];
                bl[nt][0] = *(const uint32_t*)&sBl[koff];
                bl[nt][1] = *(const uint32_t*)&sBl[koff + 8];
            }
            #pragma unroll
            for (int mt = 0; mt < 4; mt++) {
                const int ar = warp_m * 64 + mt * 16 + g;
                const int ao = ar * ASTR + kb + cq;
                uint32_t ah[4], al[4];
                ah[0] = *(const uint32_t*)&sAh[ao];
                ah[1] = *(const uint32_t*)&sAh[ao + 8 * ASTR];
                ah[2] = *(const uint32_t*)&sAh[ao + 8];
                ah[3] = *(const uint32_t*)&sAh[ao + 8 * ASTR + 8];
                al[0] = *(const uint32_t*)&sAl[ao];
                al[1] = *(const uint32_t*)&sAl[ao + 8 * ASTR];
                al[2] = *(const uint32_t*)&sAl[ao + 8];
                al[3] = *(const uint32_t*)&sAl[ao + 8 * ASTR + 8];
                #pragma unroll
                for (int nt = 0; nt < 4; nt++) {
                    mma16816(acc[mt][nt], ah, bh[nt]);
                    mma16816(acc[mt][nt], ah, bl[nt]);
                    mma16816(acc[mt][nt], al, bh[nt]);
                }
            }
        }
        __syncthreads();
    }

    #pragma unroll
    for (int mt = 0; mt < 4; mt++) {
        #pragma unroll
        for (int nt = 0; nt < 4; nt++) {
            const int row0 = bm + warp_m * 64 + mt * 16 + g;
            const int col  = bn + warp_n * 32 + nt * 8 + cq;
            #pragma unroll
            for (int half = 0; half < 2; half++) {
                const int row = row0 + half * 8;
                float v0 = acc[mt][nt][half * 2 + 0];
                float v1 = acc[mt][nt][half * 2 + 1];
                if (EPI == 1) {
                    v0 = v0 / (1.0f + expf(-v0));
                    v1 = v1 / (1.0f + expf(-v1));
                }
                if (EPI == 2) {
                    const int bb = row >> 12, nn = row & 4095;
                    const int hh = col >> 9,  ee = col & 511;
                    float2* p = (float2*)(g_v + (((size_t)(bb * H_ + hh)) * NSEQ + nn) * DV + ee);
                    *p = make_float2(v0, v1);
                } else {
                    float2* p = (float2*)(C + (size_t)row * Ncols + col);
                    *p = make_float2(v0, v1);
                }
            }
        }
    }
}

// ---------------- weight transpose + bf16 split ----------------
__global__ void wsplitT(const float* __restrict__ W, __nv_bfloat16* __restrict__ Th,
                        __nv_bfloat16* __restrict__ Tl, int K, int N)
{
    __shared__ float t[32][33];
    const int n0 = blockIdx.x * 32, k0 = blockIdx.y * 32;
    const int tx = threadIdx.x, ty = threadIdx.y;
    #pragma unroll
    for (int i = 0; i < 4; i++)
        t[ty * 4 + i][tx] = W[(size_t)(k0 + ty * 4 + i) * N + n0 + tx];
    __syncthreads();
    #pragma unroll
    for (int i = 0; i < 4; i++) {
        const int r = ty * 4 + i;
        const float v = t[tx][r];
        const __nv_bfloat16 h = __float2bfloat16(v);
        const __nv_bfloat16 l = __float2bfloat16(v - __bfloat162float(h));
        Th[(size_t)(n0 + r) * K + k0 + tx] = h;
        Tl[(size_t)(n0 + r) * K + k0 + tx] = l;
    }
}

// ---------------- row-major bf16 split (activations) ----------------
__global__ void split_rows(const float* __restrict__ A, __nv_bfloat16* __restrict__ H,
                           __nv_bfloat16* __restrict__ L)
{
    const int i = blockIdx.x * blockDim.x + threadIdx.x;
    const float4 v = ((const float4*)A)[i];
    const __nv_bfloat16 h0 = __float2bfloat16(v.x);
    const __nv_bfloat16 h1 = __float2bfloat16(v.y);
    const __nv_bfloat16 h2 = __float2bfloat16(v.z);
    const __nv_bfloat16 h3 = __float2bfloat16(v.w);
    ((__nv_bfloat162*)H)[i * 2 + 0] = __halves2bfloat162(h0, h1);
    ((__nv_bfloat162*)H)[i * 2 + 1] = __halves2bfloat162(h2, h3);
    const __nv_bfloat16 l0 = __float2bfloat16(v.x - __bfloat162float(h0));
    const __nv_bfloat16 l1 = __float2bfloat16(v.y - __bfloat162float(h1));
    const __nv_bfloat16 l2 = __float2bfloat16(v.z - __bfloat162float(h2));
    const __nv_bfloat16 l3 = __float2bfloat16(v.w - __bfloat162float(h3));
    ((__nv_bfloat162*)L)[i * 2 + 0] = __halves2bfloat162(l0, l1);
    ((__nv_bfloat162*)L)[i * 2 + 1] = __halves2bfloat162(l2, l3);
}

// ---------------- rotary table ----------------
__global__ void rope_table(float* __restrict__ cosT, float* __restrict__ sinT)
{
    const int t = blockIdx.x;
    const int i = threadIdx.x;
    const double m = (double)i * (1.0 / 128.0);
    const double invf = exp(-m * 9.210340371976184);
    const float pf = (float)t * (float)invf;
    const double ph = (double)pf;
    const double kq = rint(ph * 0.15915494309189535);
    const float rf = (float)(ph - kq * 6.283185307179586);
    cosT[t * 128 + i] = cosf(rf);
    sinT[t * 128 + i] = sinf(rf);
}

// ---------------- rotary + transpose to (B,H,N,dk), q scaled ----------------
__global__ void rope_apply(const float* __restrict__ Q1, const float* __restrict__ K1,
                           float* __restrict__ Qo, float* __restrict__ Ko,
                           const float* __restrict__ cosT, const float* __restrict__ sinT)
{
    const int idx = blockIdx.x * blockDim.x + threadIdx.x;
    const int i  = idx & 127;
    const int hh = (idx >> 7) & 3;
    const int n  = (idx >> 9) & 4095;
    const int b  = idx >> 21;
    const float cv = cosT[n * 128 + i];
    const float sv = sinT[n * 128 + i];
    const size_t src = ((size_t)(b * NSEQ + n)) * DM + hh * DK + i;
    const size_t dst = (((size_t)(b * H_ + hh)) * NSEQ + n) * DK + i;

    const float qa = Q1[src], qb = Q1[src + 128];
    Qo[dst]       = (qa * cv - qb * sv) * 0.0625f;
    Qo[dst + 128] = (qb * cv + qa * sv) * 0.0625f;
    const float ka = K1[src], kb = K1[src + 128];
    Ko[dst]       = ka * cv - kb * sv;
    Ko[dst + 128] = kb * cv + ka * sv;
}

// =====================================================================
//  phase A (mma): Ut[e][d] = sum_j V[j][e] * (K[j][d] * gamma^(63-j))
//  block: z chunk, e-block 128 (x), d-block 128 (y). 256 threads.
// =====================================================================
#define RSTR 72
#define CKV_DSMEM (4 * 128 * RSTR * 2)   // vTh, vTl, kTh, kTl

__global__ __launch_bounds__(256)
void chunk_kv_mma(const float* __restrict__ K, const float* __restrict__ V,
                  float* __restrict__ U)
{
    extern __shared__ __nv_bfloat16 sm[];
    __nv_bfloat16* vTh = sm;
    __nv_bfloat16* vTl = sm + 128 * RSTR;
    __nv_bfloat16* kTh = sm + 2 * 128 * RSTR;
    __nv_bfloat16* kTl = sm + 3 * 128 * RSTR;
    __shared__ float gj[64];

    const int tid = threadIdx.x;
    const int wid = tid >> 5, lane = tid & 31;
    const int g = lane >> 2, cq = (lane & 3) * 2;
    const int warp_m = wid & 1;      // e: 2 x 64
    const int warp_n = wid >> 1;     // d: 4 x 32

    const int z = blockIdx.z;
    const int bh = z >> 6, c = z & 63;
    const int hd = bh & 3;
    const int e0 = blockIdx.x * 128;
    const int d0 = blockIdx.y * 128;
    const float gamma = 1.0f - exp2f(-(float)(5 + hd));
    if (tid < 64) gj[tid] = powf(gamma, (float)(63 - tid));
    __syncthreads();

    const float* kptr = K + ((size_t)bh * NSEQ + c * 64) * DK;
    const float* vptr = V + ((size_t)bh * NSEQ + c * 64) * DV;

    // transposed loads: j = tid>>2, 32 cols each
    {
        const int j = tid >> 2;
        const int c0 = (tid & 3) * 32;
        const float sk = gj[j];
        #pragma unroll
        for (int u = 0; u < 8; u++) {
            float4 vv = *(const float4*)(vptr + (size_t)j * DV + e0 + c0 + u * 4);
            const float va[4] = {vv.x, vv.y, vv.z, vv.w};
            #pragma unroll
            for (int x = 0; x < 4; x++)
                split_store(vTh, vTl, (c0 + u * 4 + x) * RSTR + j, va[x]);
            float4 kk = *(const float4*)(kptr + (size_t)j * DK + d0 + c0 + u * 4);
            const float ka[4] = {kk.x * sk, kk.y * sk, kk.z * sk, kk.w * sk};
            #pragma unroll
            for (int x = 0; x < 4; x++)
                split_store(kTh, kTl, (c0 + u * 4 + x) * RSTR + j, ka[x]);
        }
    }
    __syncthreads();

    float acc[4][4][4];
    #pragma unroll
    for (int mt = 0; mt < 4; mt++)
        #pragma unroll
        for (int nt = 0; nt < 4; nt++)
            #pragma unroll
            for (int r = 0; r < 4; r++) acc[mt][nt][r] = 0.0f;

    #pragma unroll
    for (int ks = 0; ks < 4; ks++) {
        const int kb = ks * 16;
        uint32_t bh_[4][2], bl_[4][2];
        #pragma unroll
        for (int nt = 0; nt < 4; nt++) {
            const int nrow = warp_n * 32 + nt * 8 + g;
            const int ko = nrow * RSTR + kb + cq;
            bh_[nt][0] = *(const uint32_t*)&kTh[ko];
            bh_[nt][1] = *(const uint32_t*)&kTh[ko + 8];
            bl_[nt][0] = *(const uint32_t*)&kTl[ko];
            bl_[nt][1] = *(const uint32_t*)&kTl[ko + 8];
        }
        #pragma unroll
        for (int mt = 0; mt < 4; mt++) {
            const int mrow = warp_m * 64 + mt * 16 + g;
            const int ao = mrow * RSTR + kb + cq;
            uint32_t ah[4], al[4];
            ah[0] = *(const uint32_t*)&vTh[ao];
            ah[1] = *(const uint32_t*)&vTh[ao + 8 * RSTR];
            ah[2] = *(const uint32_t*)&vTh[ao + 8];
            ah[3] = *(const uint32_t*)&vTh[ao + 8 * RSTR + 8];
            al[0] = *(const uint32_t*)&vTl[ao];
            al[1] = *(const uint32_t*)&vTl[ao + 8 * RSTR];
            al[2] = *(const uint32_t*)&vTl[ao + 8];
            al[3] = *(const uint32_t*)&vTl[ao + 8 * RSTR + 8];
            #pragma unroll
            for (int nt = 0; nt < 4; nt++) {
                mma16816(acc[mt][nt], ah, bh_[nt]);
                mma16816(acc[mt][nt], ah, bl_[nt]);
                mma16816(acc[mt][nt], al, bh_[nt]);
            }
        }
    }

    float* uptr = U + (size_t)z * DK * DV;
    #pragma unroll
    for (int mt = 0; mt < 4; mt++) {
        #pragma unroll
        for (int nt = 0; nt < 4; nt++) {
            const int e = e0 + warp_m * 64 + mt * 16 + g;
            const int d = d0 + warp_n * 32 + nt * 8 + cq;
            #pragma unroll
            for (int half = 0; half < 2; half++) {
                float2* p = (float2*)(uptr + (size_t)(e + half * 8) * DK + d);
                *p = make_float2(acc[mt][nt][half * 2], acc[mt][nt][half * 2 + 1]);
            }
        }
    }
}

// ---------------- phase B: decay scan, emits S as bf16 hi/lo ----------------
__global__ void scan_state(const float* __restrict__ U,
                           __nv_bfloat16* __restrict__ Sh, __nv_bfloat16* __restrict__ Sl)
{
    const int idx = blockIdx.x * blockDim.x + threadIdx.x;   // 8*512*128
    const int d2 = (idx & 127) * 2;
    const int e  = (idx >> 7) & 511;
    const int bh = idx >> 16;
    const int hd = bh & 3;
    const float gamma = 1.0f - exp2f(-(float)(5 + hd));
    const float gC = powf(gamma, 64.0f);
    const size_t base = ((size_t)bh * 64) * (DK * DV) + (size_t)e * DK + d2;
    float s0 = 0.0f, s1 = 0.0f;
    for (int c = 0; c < 64; c++) {
        const size_t off = base + (size_t)c * (DK * DV);
        const __nv_bfloat16 h0 = __float2bfloat16(s0);
        const __nv_bfloat16 h1 = __float2bfloat16(s1);
        *(__nv_bfloat162*)(Sh + off) = __halves2bfloat162(h0, h1);
        *(__nv_bfloat162*)(Sl + off) = __halves2bfloat162(
            __float2bfloat16(s0 - __bfloat162float(h0)),
            __float2bfloat16(s1 - __bfloat162float(h1)));
        const float2 u = *(const float2*)(U + off);
        s0 = gC * s0 + u.x;
        s1 = gC * s1 + u.y;
    }
}

// =====================================================================
//  phase C (mma): o = mask(q k^T) V + (q * gamma^(i+1)) S
//  block: z chunk (y), e-block 128 (x). 256 threads (8 warps).
// =====================================================================
#define RET_BUFA 27648                      // elems: phase buffers
#define RET_DSMEM ((RET_BUFA + 2 * 4608) * 2)

__global__ __launch_bounds__(256)
void retention_mma(const float* __restrict__ Q, const float* __restrict__ Kp,
                   const float* __restrict__ V,
                   const __nv_bfloat16* __restrict__ Sh, const __nv_bfloat16* __restrict__ Sl,
                   float* __restrict__ O)
{
    extern __shared__ __nv_bfloat16 sm[];
    __nv_bfloat16* bufA  = sm;
    __nv_bfloat16* attnh = sm + RET_BUFA;
    __nv_bfloat16* attnl = sm + RET_BUFA + 4608;
    __shared__ float gpow[72];

    const int tid = threadIdx.x;
    const int wid = tid >> 5, lane = tid & 31;
    const int g = lane >> 2, cq = (lane & 3) * 2;

    const int z = blockIdx.y;
    const int bh = z >> 6, c = z & 63;
    const int hd = bh & 3, b = bh >> 2;
    const int e0 = blockIdx.x * 128;
    const float gamma = 1.0f - exp2f(-(float)(5 + hd));
    if (tid < 66) gpow[tid] = powf(gamma, (float)tid);
    __syncthreads();

    const float* qptr = Q + ((size_t)bh * NSEQ + c * 64) * DK;
    const float* kptr = Kp + ((size_t)bh * NSEQ + c * 64) * DK;
    const float* vptr = V + ((size_t)bh * NSEQ + c * 64) * DV;
    const size_t soff = (size_t)z * DK * DV;

    // ---------------- phase 1: attn = q k^T (m64 n64 k256) ----------------
    const int w_i = wid & 1;     // 2 x 32 rows
    const int w_j = wid >> 1;    // 4 x 16 cols
    float acc_a[2][2][4];
    #pragma unroll
    for (int mt = 0; mt < 2; mt++)
        #pragma unroll
        for (int nt = 0; nt < 2; nt++)
            #pragma unroll
            for (int r = 0; r < 4; r++) acc_a[mt][nt][r] = 0.0f;

    __nv_bfloat16* qh = bufA;
    __nv_bfloat16* ql = bufA + 4608;
    __nv_bfloat16* kh = bufA + 9216;
    __nv_bfloat16* kl = bufA + 13824;

    const int lrow = tid >> 2;          // 0..63
    const int lc0  = (tid & 3) * 16;

    for (int dc = 0; dc < 4; dc++) {
        const int dbase = dc * 64;
        #pragma unroll
        for (int u = 0; u < 4; u++) {
            float4 qv = *(const float4*)(qptr + (size_t)lrow * DK + dbase + lc0 + u * 4);
            const float qa[4] = {qv.x, qv.y, qv.z, qv.w};
            #pragma unroll
            for (int x = 0; x < 4; x++)
                split_store(qh, ql, lrow * RSTR + lc0 + u * 4 + x, qa[x]);
            float4 kv = *(const float4*)(kptr + (size_t)lrow * DK + dbase + lc0 + u * 4);
            const float ka[4] = {kv.x, kv.y, kv.z, kv.w};
            #pragma unroll
            for (int x = 0; x < 4; x++)
                split_store(kh, kl, lrow * RSTR + lc0 + u * 4 + x, ka[x]);
        }
        __syncthreads();

        #pragma unroll
        for (int ks = 0; ks < 4; ks++) {
            const int kb = ks * 16;
            uint32_t bh_[2][2], bl_[2][2];
            #pragma unroll
            for (int nt = 0; nt < 2; nt++) {
                const int nrow = w_j * 16 + nt * 8 + g;
                const int ko = nrow * RSTR + kb + cq;
                bh_[nt][0] = *(const uint32_t*)&kh[ko];
                bh_[nt][1] = *(const uint32_t*)&kh[ko + 8];
                bl_[nt][0] = *(const uint32_t*)&kl[ko];
                bl_[nt][1] = *(const uint32_t*)&kl[ko + 8];
            }
            #pragma unroll
            for (int mt = 0; mt < 2; mt++) {
                const int mrow = w_i * 32 + mt * 16 + g;
                const int ao = mrow * RSTR + kb + cq;
                uint32_t ah[4], al[4];
                ah[0] = *(const uint32_t*)&qh[ao];
                ah[1] = *(const uint32_t*)&qh[ao + 8 * RSTR];
                ah[2] = *(const uint32_t*)&qh[ao + 8];
                ah[3] = *(const uint32_t*)&qh[ao + 8 * RSTR + 8];
                al[0] = *(const uint32_t*)&ql[ao];
                al[1] = *(const uint32_t*)&ql[ao + 8 * RSTR];
                al[2] = *(const uint32_t*)&ql[ao + 8];
                al[3] = *(const uint32_t*)&ql[ao + 8 * RSTR + 8];
                #pragma unroll
                for (int nt = 0; nt < 2; nt++) {
                    mma16816(acc_a[mt][nt], ah, bh_[nt]);
                    mma16816(acc_a[mt][nt], ah, bl_[nt]);
                    mma16816(acc_a[mt][nt], al, bh_[nt]);
                }
            }
        }
        __syncthreads();
    }

    // mask + decay, store attn as bf16 split
    #pragma unroll
    for (int mt = 0; mt < 2; mt++)
        #pragma unroll
        for (int nt = 0; nt < 2; nt++)
            #pragma unroll
            for (int half = 0; half < 2; half++) {
                const int i = w_i * 32 + mt * 16 + g + half * 8;
                #pragma unroll
                for (int x = 0; x < 2; x++) {
                    const int j = w_j * 16 + nt * 8 + cq + x;
                    const float v = (i >= j) ? acc_a[mt][nt][half * 2 + x] * gpow[i - j] : 0.0f;
                    split_store(attnh, attnl, i * RSTR + j, v);
                }
            }
    __syncthreads();

    // ---------------- phase 2: o += attn @ V (m64 n128 k64) ----------------
    const int w_i2 = wid & 1;     // 2 x 32 rows
    const int w_e  = wid >> 1;    // 4 x 32 cols
    float acc_o[2][4][4];
    #pragma unroll
    for (int mt = 0; mt < 2; mt++)
        #pragma unroll
        for (int nt = 0; nt < 4; nt++)
            #pragma unroll
            for (int r = 0; r < 4; r++) acc_o[mt][nt][r] = 0.0f;

    __nv_bfloat16* vTh = bufA;
    __nv_bfloat16* vTl = bufA + 9216;
    {
        const int j = tid >> 2;
        const int c0 = (tid & 3) * 32;
        #pragma unroll
        for (int u = 0; u < 8; u++) {
            float4 vv = *(const float4*)(vptr + (size_t)j * DV + e0 + c0 + u * 4);
            const float va[4] = {vv.x, vv.y, vv.z, vv.w};
            #pragma unroll
            for (int x = 0; x < 4; x++)
                split_store(vTh, vTl, (c0 + u * 4 + x) * RSTR + j, va[x]);
        }
    }
    __syncthreads();

    #pragma unroll
    for (int ks = 0; ks < 4; ks++) {
        const int kb = ks * 16;
        uint32_t bh_[4][2], bl_[4][2];
        #pragma unroll
        for (int nt = 0; nt < 4; nt++) {
            const int nrow = w_e * 32 + nt * 8 + g;
            const int ko = nrow * RSTR + kb + cq;
            bh_[nt][0] = *(const uint32_t*)&vTh[ko];
            bh_[nt][1] = *(const uint32_t*)&vTh[ko + 8];
            bl_[nt][0] = *(const uint32_t*)&vTl[ko];
            bl_[nt][1] = *(const uint32_t*)&vTl[ko + 8];
        }
        #pragma unroll
        for (int mt = 0; mt < 2; mt++) {
            const int mrow = w_i2 * 32 + mt * 16 + g;
            const int ao = mrow * RSTR + kb + cq;
            uint32_t ah[4], al[4];
            ah[0] = *(const uint32_t*)&attnh[ao];
            ah[1] = *(const uint32_t*)&attnh[ao + 8 * RSTR];
            ah[2] = *(const uint32_t*)&attnh[ao + 8];
            ah[3] = *(const uint32_t*)&attnh[ao + 8 * RSTR + 8];
            al[0] = *(const uint32_t*)&attnl[ao];
            al[1] = *(const uint32_t*)&attnl[ao + 8 * RSTR];
            al[2] = *(const uint32_t*)&attnl[ao + 8];
            al[3] = *(const uint32_t*)&attnl[ao + 8 * RSTR + 8];
            #pragma unroll
            for (int nt = 0; nt < 4; nt++) {
                mma16816(acc_o[mt][nt], ah, bh_[nt]);
                mma16816(acc_o[mt][nt], ah, bl_[nt]);
                mma16816(acc_o[mt][nt], al, bh_[nt]);
            }
        }
    }
    __syncthreads();

    // ---------------- phase 3: o += (q * gamma^(i+1)) @ S (m64 n128 k256) ----------------
    __nv_bfloat16* qch = bufA;
    __nv_bfloat16* qcl = bufA + 4608;
    __nv_bfloat16* sth = bufA + 9216;
    __nv_bfloat16* stl = bufA + 18432;

    for (int dc = 0; dc < 4; dc++) {
        const int dbase = dc * 64;
        // qc load (row = i)
        {
            const float sc = gpow[lrow + 1];
            #pragma unroll
            for (int u = 0; u < 4; u++) {
                float4 qv = *(const float4*)(qptr + (size_t)lrow * DK + dbase + lc0 + u * 4);
                const float qa[4] = {qv.x * sc, qv.y * sc, qv.z * sc, qv.w * sc};
                #pragma unroll
                for (int x = 0; x < 4; x++)
                    split_store(qch, qcl, lrow * RSTR + lc0 + u * 4 + x, qa[x]);
            }
        }
        // St tiles: rows e (128), cols d (64), natural layout — direct uint4 copies
        {
            const int e = tid >> 1;
            const int c0 = (tid & 1) * 32;
            const size_t gsrc = soff + (size_t)(e0 + e) * DK + dbase + c0;
            #pragma unroll
            for (int u = 0; u < 4; u++) {
                *(uint4*)&sth[e * RSTR + c0 + u * 8] = *(const uint4*)(Sh + gsrc + u * 8);
                *(uint4*)&stl[e * RSTR + c0 + u * 8] = *(const uint4*)(Sl + gsrc + u * 8);
            }
        }
        __syncthreads();

        #pragma unroll
        for (int ks = 0; ks < 4; ks++) {
            const int kb = ks * 16;
            uint32_t bh_[4][2], bl_[4][2];
            #pragma unroll
            for (int nt = 0; nt < 4; nt++) {
                const int nrow = w_e * 32 + nt * 8 + g;
                const int ko = nrow * RSTR + kb + cq;
                bh_[nt][0] = *(const uint32_t*)&sth[ko];
                bh_[nt][1] = *(const uint32_t*)&sth[ko + 8];
                bl_[nt][0] = *(const uint32_t*)&stl[ko];
                bl_[nt][1] = *(const uint32_t*)&stl[ko + 8];
            }
            #pragma unroll
            for (int mt = 0; mt < 2; mt++) {
                const int mrow = w_i2 * 32 + mt * 16 + g;
                const int ao = mrow * RSTR + kb + cq;
                uint32_t ah[4], al[4];
                ah[0] = *(const uint32_t*)&qch[ao];
                ah[1] = *(const uint32_t*)&qch[ao + 8 * RSTR];
                ah[2] = *(const uint32_t*)&qch[ao + 8];
                ah[3] = *(const uint32_t*)&qch[ao + 8 * RSTR + 8];
                al[0] = *(const uint32_t*)&qcl[ao];
                al[1] = *(const uint32_t*)&qcl[ao + 8 * RSTR];
                al[2] = *(const uint32_t*)&qcl[ao + 8];
                al[3] = *(const uint32_t*)&qcl[ao + 8 * RSTR + 8];
                #pragma unroll
                for (int nt = 0; nt < 4; nt++) {
                    mma16816(acc_o[mt][nt], ah, bh_[nt]);
                    mma16816(acc_o[mt][nt], ah, bl_[nt]);
                    mma16816(acc_o[mt][nt], al, bh_[nt]);
                }
            }
        }
        __syncthreads();
    }

    // epilogue: O in (B,N,H,dv)
    #pragma unroll
    for (int mt = 0; mt < 2; mt++)
        #pragma unroll
        for (int nt = 0; nt < 4; nt++)
            #pragma unroll
            for (int half = 0; half < 2; half++) {
                const int i = w_i2 * 32 + mt * 16 + g + half * 8;
                const int e = e0 + w_e * 32 + nt * 8 + cq;
                float2* p = (float2*)(O + (((size_t)(b * NSEQ + c * 64 + i)) * H_ + hd) * DV + e);
                *p = make_float2(acc_o[mt][nt][half * 2], acc_o[mt][nt][half * 2 + 1]);
            }
}

// ---------------- rmsnorm * silu-gate -> bf16 hi/lo for Wo GEMM ----------------
__global__ void norm_gate(const float* __restrict__ O, const float* __restrict__ G,
                          const float* __restrict__ w,
                          __nv_bfloat16* __restrict__ Gh, __nv_bfloat16* __restrict__ Gl)
{
    __shared__ float red[4];
    const int row = blockIdx.x;
    const int tid = threadIdx.x;
    const size_t base = (size_t)row * DV;

    float4 x = *(const float4*)(O + base + tid * 4);
    float ss = x.x * x.x + x.y * x.y + x.z * x.z + x.w * x.w;
    #pragma unroll
    for (int off = 16; off; off >>= 1) ss += __shfl_xor_sync(0xffffffff, ss, off);
    if ((tid & 31) == 0) red[tid >> 5] = ss;
    __syncthreads();
    const float tot = red[0] + red[1] + red[2] + red[3];
    const float inv = rsqrtf(tot * (1.0f / (float)DV) + 1e-5f);

    float4 wv = *(const float4*)(w + tid * 4);
    float4 gv = *(const float4*)(G + base + tid * 4);
    float o0 = x.x * inv * wv.x * gv.x;
    float o1 = x.y * inv * wv.y * gv.y;
    float o2 = x.z * inv * wv.z * gv.z;
    float o3 = x.w * inv * wv.w * gv.w;

    const __nv_bfloat16 h0 = __float2bfloat16(o0);
    const __nv_bfloat16 h1 = __float2bfloat16(o1);
    const __nv_bfloat16 h2 = __float2bfloat16(o2);
    const __nv_bfloat16 h3 = __float2bfloat16(o3);
    const size_t p = (base >> 1) + tid * 2;
    ((__nv_bfloat162*)Gh)[p + 0] = __halves2bfloat162(h0, h1);
    ((__nv_bfloat162*)Gh)[p + 1] = __halves2bfloat162(h2, h3);
    ((__nv_bfloat162*)Gl)[p + 0] = __halves2bfloat162(
        __float2bfloat16(o0 - __bfloat162float(h0)), __float2bfloat16(o1 - __bfloat162float(h1)));
    ((__nv_bfloat162*)Gl)[p + 1] = __halves2bfloat162(
        __float2bfloat16(o2 - __bfloat162float(h2)), __float2bfloat16(o3 - __bfloat162float(h3)));
}

// ---------------- launch ----------------
extern "C" void kernel_launch(void* const* d_in, const int* in_sizes, int n_in,
                              void* d_out, int out_size)
{
    const float* x  = (const float*)d_in[0];
    const float* Wq = (const float*)d_in[1];
    const float* Wk = (const float*)d_in[2];
    const float* Wv = (const float*)d_in[3];
    const float* Wg = (const float*)d_in[4];
    const float* Wo = (const float*)d_in[5];
    const float* gw = (const float*)d_in[6];
    float* out = (float*)d_out;

    float *q1, *k1, *q, *k, *v, *g, *o, *U, *S, *ct, *st;
    __nv_bfloat16 *xh, *xl, *wth, *wtl, *gh, *gl;
    cudaGetSymbolAddress((void**)&q1, g_q1);
    cudaGetSymbolAddress((void**)&k1, g_k1);
    cudaGetSymbolAddress((void**)&q,  g_q);
    cudaGetSymbolAddress((void**)&k,  g_k);
    cudaGetSymbolAddress((void**)&v,  g_v);
    cudaGetSymbolAddress((void**)&g,  g_g);
    cudaGetSymbolAddress((void**)&o,  g_o);
    cudaGetSymbolAddress((void**)&U,  g_U);
    cudaGetSymbolAddress((void**)&S,  g_S);
    cudaGetSymbolAddress((void**)&ct, g_cos);
    cudaGetSymbolAddress((void**)&st, g_sin);
    cudaGetSymbolAddress((void**)&xh, g_xh);
    cudaGetSymbolAddress((void**)&xl, g_xl);
    cudaGetSymbolAddress((void**)&wth, g_wth);
    cudaGetSymbolAddress((void**)&wtl, g_wtl);
    cudaGetSymbolAddress((void**)&gh, g_gh);
    cudaGetSymbolAddress((void**)&gl, g_gl);

    __nv_bfloat16* Sh = (__nv_bfloat16*)S;
    __nv_bfloat16* Sl = Sh + SELEMS;

    cudaFuncSetAttribute(gemm_mma<0>, cudaFuncAttributeMaxDynamicSharedMemorySize, GEMM_DSMEM);
    cudaFuncSetAttribute(gemm_mma<1>, cudaFuncAttributeMaxDynamicSharedMemorySize, GEMM_DSMEM);
    cudaFuncSetAttribute(gemm_mma<2>, cudaFuncAttributeMaxDynamicSharedMemorySize, GEMM_DSMEM);
    cudaFuncSetAttribute(chunk_kv_mma, cudaFuncAttributeMaxDynamicSharedMemorySize, CKV_DSMEM);
    cudaFuncSetAttribute(retention_mma, cudaFuncAttributeMaxDynamicSharedMemorySize, RET_DSMEM);

    const int M = B_ * NSEQ;  // 8192

    // bf16 splits: activations + transposed weights
    split_rows<<<(M * DM / 4) / 256, 256>>>(x, xh, xl);
    wsplitT<<<dim3(DM / 32, DM / 32), dim3(32, 8)>>>(Wq, wth + WOFF_Q, wtl + WOFF_Q, DM, DM);
    wsplitT<<<dim3(DM / 32, DM / 32), dim3(32, 8)>>>(Wk, wth + WOFF_K, wtl + WOFF_K, DM, DM);
    wsplitT<<<dim3(VD / 32, DM / 32), dim3(32, 8)>>>(Wv, wth + WOFF_V, wtl + WOFF_V, DM, VD);
    wsplitT<<<dim3(VD / 32, DM / 32), dim3(32, 8)>>>(Wg, wth + WOFF_G, wtl + WOFF_G, DM, VD);
    wsplitT<<<dim3(DM / 32, VD / 32), dim3(32, 8)>>>(Wo, wth + WOFF_O, wtl + WOFF_O, VD, DM);

    // tensor-pipe projections
    gemm_mma<0><<<dim3(DM / BN, M / BM), 256, GEMM_DSMEM>>>(xh, xl, wth + WOFF_Q, wtl + WOFF_Q, q1, M, DM, DM);
    gemm_mma<0><<<dim3(DM / BN, M / BM), 256, GEMM_DSMEM>>>(xh, xl, wth + WOFF_K, wtl + WOFF_K, k1, M, DM, DM);
    gemm_mma<2><<<dim3(VD / BN, M / BM), 256, GEMM_DSMEM>>>(xh, xl, wth + WOFF_V, wtl + WOFF_V, v, M, VD, DM);
    gemm_mma<1><<<dim3(VD / BN, M / BM), 256, GEMM_DSMEM>>>(xh, xl, wth + WOFF_G, wtl + WOFF_G, g, M, VD, DM);

    // rotary
    rope_table<<<NSEQ, 128>>>(ct, st);
    rope_apply<<<(B_ * NSEQ * H_ * 128) / 256, 256>>>(q1, k1, q, k, ct, st);

    // retention on tensor pipe
    chunk_kv_mma<<<dim3(DV / 128, DK / 128, B_ * H_ * NC), 256, CKV_DSMEM>>>(k, v, U);
    scan_state<<<(B_ * H_ * DV * (DK / 2)) / 256, 256>>>(U, Sh, Sl);
    retention_mma<<<dim3(DV / 128, B_ * H_ * NC), 256, RET_DSMEM>>>(q, k, v, Sh, Sl, o);

    // rmsnorm + gate, then output projection
    norm_gate<<<B_ * NSEQ * H_, 128>>>(o, g, gw, gh, gl);
    gemm_mma<0><<<dim3(DM / BN, M / BM), 256, GEMM_DSMEM>>>(gh, gl, wth + WOFF_O, wtl + WOFF_O, out, M, DM, VD);
}

// round 17
// speedup vs baseline: 1.0017x; 1.0009x over previous
#include <cuda_runtime.h>
#include <cuda_bf16.h>
#include <math.h>
#include <stdint.h>

#define B_    2
#define NSEQ  4096
#define H_    4
#define DK    256
#define DV    512
#define DM    1024
#define VD    2048
#define NC    64

// ---------------- static scratch (allocation-free rule) ----------------
__device__ float g_q1[(size_t)B_ * NSEQ * DM];
__device__ float g_k1[(size_t)B_ * NSEQ * DM];
__device__ float g_q [(size_t)B_ * NSEQ * DM];
__device__ float g_k [(size_t)B_ * NSEQ * DM];
__device__ float g_v [(size_t)B_ * NSEQ * VD];
__device__ float g_g [(size_t)B_ * NSEQ * VD];
__device__ float g_o [(size_t)B_ * NSEQ * VD];
__device__ float g_U [(size_t)B_ * H_ * NC * DK * DV];   // Ut layout: [bh][c][e][d]
__device__ float g_S [(size_t)B_ * H_ * NC * DK * DV];   // aliased: Sh | Sl (bf16 each)
__device__ float g_cos[(size_t)NSEQ * 128];
__device__ float g_sin[(size_t)NSEQ * 128];

// bf16-split operands
__device__ __nv_bfloat16 g_xh[(size_t)B_ * NSEQ * DM];
__device__ __nv_bfloat16 g_xl[(size_t)B_ * NSEQ * DM];
__device__ __nv_bfloat16 g_wth[8388608];
__device__ __nv_bfloat16 g_wtl[8388608];
__device__ __nv_bfloat16 g_gh[(size_t)B_ * NSEQ * VD];
__device__ __nv_bfloat16 g_gl[(size_t)B_ * NSEQ * VD];

#define WOFF_Q 0
#define WOFF_K 1048576
#define WOFF_V 2097152
#define WOFF_G 4194304
#define WOFF_O 6291456

#define SELEMS ((size_t)B_ * H_ * NC * DK * DV)   // 67108864 elems

// =====================================================================
//  shared mma helpers
// =====================================================================
__device__ __forceinline__ void mma16816(float* d, const uint32_t* a, const uint32_t* b) {
    asm volatile(
        "mma.sync.aligned.m16n8k16.row.col.f32.bf16.bf16.f32 "
        "{%0,%1,%2,%3}, {%4,%5,%6,%7}, {%8,%9}, {%0,%1,%2,%3};"
        : "+f"(d[0]), "+f"(d[1]), "+f"(d[2]), "+f"(d[3])
        : "r"(a[0]), "r"(a[1]), "r"(a[2]), "r"(a[3]), "r"(b[0]), "r"(b[1]));
}
__device__ __forceinline__ void cpa16(uint32_t dst, const void* src) {
    asm volatile("cp.async.cg.shared.global [%0], [%1], 16;" :: "r"(dst), "l"(src));
}
__device__ __forceinline__ void cpa_commit() {
    asm volatile("cp.async.commit_group;" ::: "memory");
}
template <int N>
__device__ __forceinline__ void cpa_wait() {
    asm volatile("cp.async.wait_group %0;" :: "n"(N) : "memory");
}
__device__ __forceinline__ void split_store(__nv_bfloat16* H, __nv_bfloat16* L, int idx, float v) {
    const __nv_bfloat16 h = __float2bfloat16(v);
    H[idx] = h;
    L[idx] = __float2bfloat16(v - __bfloat162float(h));
}

// =====================================================================
//  warp-MMA GEMM with cp.async 2-stage pipeline (unchanged from R11)
// =====================================================================
#define BM 128
#define BN 128
#define BK 32
#define ASTR 40
#define TILE_E (BM * ASTR)
#define STG_E  (4 * TILE_E)
#define GEMM_DSMEM (2 * STG_E * 2)

template <int EPI>
__global__ __launch_bounds__(256)
void gemm_mma(const __nv_bfloat16* __restrict__ Ah, const __nv_bfloat16* __restrict__ Al,
              const __nv_bfloat16* __restrict__ Bh, const __nv_bfloat16* __restrict__ Bl,
              float* __restrict__ C, int M, int Ncols, int K)
{
    extern __shared__ __nv_bfloat16 dyn[];

    const int tid = threadIdx.x;
    const int wid = tid >> 5, lane = tid & 31;
    const int warp_m = wid & 1;
    const int warp_n = wid >> 1;
    const int bm = blockIdx.y * BM;
    const int bn = blockIdx.x * BN;

    const int lrow = tid >> 1;
    const int lk   = (tid & 1) * 16;
    const int so   = lrow * ASTR + lk;

    const int g  = lane >> 2;
    const int cq = (lane & 3) * 2;

    float acc[4][4][4];
    #pragma unroll
    for (int mt = 0; mt < 4; mt++)
        #pragma unroll
        for (int nt = 0; nt < 4; nt++)
            #pragma unroll
            for (int r = 0; r < 4; r++) acc[mt][nt][r] = 0.0f;

    const int nIter = K / BK;

    auto load_stage = [&](int s, int k0) {
        __nv_bfloat16* st = dyn + s * STG_E;
        const uint32_t sb = (uint32_t)__cvta_generic_to_shared(st);
        const size_t ga = (size_t)(bm + lrow) * K + k0 + lk;
        const size_t gb = (size_t)(bn + lrow) * K + k0 + lk;
        const uint32_t d0 = sb + so * 2;
        cpa16(d0,                        Ah + ga);
        cpa16(d0 + 16,                   Ah + ga + 8);
        cpa16(d0 + TILE_E * 2,           Al + ga);
        cpa16(d0 + TILE_E * 2 + 16,      Al + ga + 8);
        cpa16(d0 + 2 * TILE_E * 2,       Bh + gb);
        cpa16(d0 + 2 * TILE_E * 2 + 16,  Bh + gb + 8);
        cpa16(d0 + 3 * TILE_E * 2,       Bl + gb);
        cpa16(d0 + 3 * TILE_E * 2 + 16,  Bl + gb + 8);
        cpa_commit();
    };

    load_stage(0, 0);

    for (int it = 0; it < nIter; it++) {
        if (it + 1 < nIter) {
            load_stage((it + 1) & 1, (it + 1) * BK);
            cpa_wait<1>();
        } else {
            cpa_wait<0>();
        }
        __syncthreads();

        const __nv_bfloat16* st  = dyn + (it & 1) * STG_E;
        const __nv_bfloat16* sAh = st;
        const __nv_bfloat16* sAl = st + TILE_E;
        const __nv_bfloat16* sBh = st + 2 * TILE_E;
        const __nv_bfloat16* sBl = st + 3 * TILE_E;

        #pragma unroll
        for (int ks = 0; ks < 2; ks++) {
            const int kb = ks * 16;
            uint32_t bh[4][2], bl[4][2];
            #pragma unroll
            for (int nt = 0; nt < 4; nt++) {
                const int nrow = warp_n * 32 + nt * 8 + g;
                const int koff = nrow * ASTR + kb + cq;
                bh[nt][0] = *(const uint32_t*)&sBh[koff];
                bh[nt][1] = *(const uint32_t*)&sBh[koff + 8];
                bl[nt][0] = *(const uint32_t*)&sBl[koff];
                bl[nt][1] = *(const uint32_t*)&sBl[koff + 8];
            }
            #pragma unroll
            for (int mt = 0; mt < 4; mt++) {
                const int ar = warp_m * 64 + mt * 16 + g;
                const int ao = ar * ASTR + kb + cq;
                uint32_t ah[4], al[4];
                ah[0] = *(const uint32_t*)&sAh[ao];
                ah[1] = *(const uint32_t*)&sAh[ao + 8 * ASTR];
                ah[2] = *(const uint32_t*)&sAh[ao + 8];
                ah[3] = *(const uint32_t*)&sAh[ao + 8 * ASTR + 8];
                al[0] = *(const uint32_t*)&sAl[ao];
                al[1] = *(const uint32_t*)&sAl[ao + 8 * ASTR];
                al[2] = *(const uint32_t*)&sAl[ao + 8];
                al[3] = *(const uint32_t*)&sAl[ao + 8 * ASTR + 8];
                #pragma unroll
                for (int nt = 0; nt < 4; nt++) {
                    mma16816(acc[mt][nt], ah, bh[nt]);
                    mma16816(acc[mt][nt], ah, bl[nt]);
                    mma16816(acc[mt][nt], al, bh[nt]);
                }
            }
        }
        __syncthreads();
    }

    #pragma unroll
    for (int mt = 0; mt < 4; mt++) {
        #pragma unroll
        for (int nt = 0; nt < 4; nt++) {
            const int row0 = bm + warp_m * 64 + mt * 16 + g;
            const int col  = bn + warp_n * 32 + nt * 8 + cq;
            #pragma unroll
            for (int half = 0; half < 2; half++) {
                const int row = row0 + half * 8;
                float v0 = acc[mt][nt][half * 2 + 0];
                float v1 = acc[mt][nt][half * 2 + 1];
                if (EPI == 1) {
                    v0 = v0 / (1.0f + expf(-v0));
                    v1 = v1 / (1.0f + expf(-v1));
                }
                if (EPI == 2) {
                    const int bb = row >> 12, nn = row & 4095;
                    const int hh = col >> 9,  ee = col & 511;
                    float2* p = (float2*)(g_v + (((size_t)(bb * H_ + hh)) * NSEQ + nn) * DV + ee);
                    *p = make_float2(v0, v1);
                } else {
                    float2* p = (float2*)(C + (size_t)row * Ncols + col);
                    *p = make_float2(v0, v1);
                }
            }
        }
    }
}

// ---------------- weight transpose + bf16 split ----------------
__global__ void wsplitT(const float* __restrict__ W, __nv_bfloat16* __restrict__ Th,
                        __nv_bfloat16* __restrict__ Tl, int K, int N)
{
    __shared__ float t[32][33];
    const int n0 = blockIdx.x * 32, k0 = blockIdx.y * 32;
    const int tx = threadIdx.x, ty = threadIdx.y;
    #pragma unroll
    for (int i = 0; i < 4; i++)
        t[ty * 4 + i][tx] = W[(size_t)(k0 + ty * 4 + i) * N + n0 + tx];
    __syncthreads();
    #pragma unroll
    for (int i = 0; i < 4; i++) {
        const int r = ty * 4 + i;
        const float v = t[tx][r];
        const __nv_bfloat16 h = __float2bfloat16(v);
        const __nv_bfloat16 l = __float2bfloat16(v - __bfloat162float(h));
        Th[(size_t)(n0 + r) * K + k0 + tx] = h;
        Tl[(size_t)(n0 + r) * K + k0 + tx] = l;
    }
}

// ---------------- row-major bf16 split (activations) ----------------
__global__ void split_rows(const float* __restrict__ A, __nv_bfloat16* __restrict__ H,
                           __nv_bfloat16* __restrict__ L)
{
    const int i = blockIdx.x * blockDim.x + threadIdx.x;
    const float4 v = ((const float4*)A)[i];
    const __nv_bfloat16 h0 = __float2bfloat16(v.x);
    const __nv_bfloat16 h1 = __float2bfloat16(v.y);
    const __nv_bfloat16 h2 = __float2bfloat16(v.z);
    const __nv_bfloat16 h3 = __float2bfloat16(v.w);
    ((__nv_bfloat162*)H)[i * 2 + 0] = __halves2bfloat162(h0, h1);
    ((__nv_bfloat162*)H)[i * 2 + 1] = __halves2bfloat162(h2, h3);
    const __nv_bfloat16 l0 = __float2bfloat16(v.x - __bfloat162float(h0));
    const __nv_bfloat16 l1 = __float2bfloat16(v.y - __bfloat162float(h1));
    const __nv_bfloat16 l2 = __float2bfloat16(v.z - __bfloat162float(h2));
    const __nv_bfloat16 l3 = __float2bfloat16(v.w - __bfloat162float(h3));
    ((__nv_bfloat162*)L)[i * 2 + 0] = __halves2bfloat162(l0, l1);
    ((__nv_bfloat162*)L)[i * 2 + 1] = __halves2bfloat162(l2, l3);
}

// ---------------- rotary table ----------------
__global__ void rope_table(float* __restrict__ cosT, float* __restrict__ sinT)
{
    const int t = blockIdx.x;
    const int i = threadIdx.x;
    const double m = (double)i * (1.0 / 128.0);
    const double invf = exp(-m * 9.210340371976184);
    const float pf = (float)t * (float)invf;
    const double ph = (double)pf;
    const double kq = rint(ph * 0.15915494309189535);
    const float rf = (float)(ph - kq * 6.283185307179586);
    cosT[t * 128 + i] = cosf(rf);
    sinT[t * 128 + i] = sinf(rf);
}

// ---------------- rotary + transpose to (B,H,N,dk), q scaled ----------------
__global__ void rope_apply(const float* __restrict__ Q1, const float* __restrict__ K1,
                           float* __restrict__ Qo, float* __restrict__ Ko,
                           const float* __restrict__ cosT, const float* __restrict__ sinT)
{
    const int idx = blockIdx.x * blockDim.x + threadIdx.x;
    const int i  = idx & 127;
    const int hh = (idx >> 7) & 3;
    const int n  = (idx >> 9) & 4095;
    const int b  = idx >> 21;
    const float cv = cosT[n * 128 + i];
    const float sv = sinT[n * 128 + i];
    const size_t src = ((size_t)(b * NSEQ + n)) * DM + hh * DK + i;
    const size_t dst = (((size_t)(b * H_ + hh)) * NSEQ + n) * DK + i;

    const float qa = Q1[src], qb = Q1[src + 128];
    Qo[dst]       = (qa * cv - qb * sv) * 0.0625f;
    Qo[dst + 128] = (qb * cv + qa * sv) * 0.0625f;
    const float ka = K1[src], kb = K1[src + 128];
    Ko[dst]       = ka * cv - kb * sv;
    Ko[dst + 128] = kb * cv + ka * sv;
}

// =====================================================================
//  phase A (mma): Ut[e][d] = sum_j V[j][e] * (K[j][d] * gamma^(63-j))
//  block: z chunk, e-block 128 (x), d-block 128 (y). 256 threads.
// =====================================================================
#define RSTR 72
#define CKV_DSMEM (4 * 128 * RSTR * 2)   // vTh, vTl, kTh, kTl

__global__ __launch_bounds__(256)
void chunk_kv_mma(const float* __restrict__ K, const float* __restrict__ V,
                  float* __restrict__ U)
{
    extern __shared__ __nv_bfloat16 sm[];
    __nv_bfloat16* vTh = sm;
    __nv_bfloat16* vTl = sm + 128 * RSTR;
    __nv_bfloat16* kTh = sm + 2 * 128 * RSTR;
    __nv_bfloat16* kTl = sm + 3 * 128 * RSTR;
    __shared__ float gj[64];

    const int tid = threadIdx.x;
    const int wid = tid >> 5, lane = tid & 31;
    const int g = lane >> 2, cq = (lane & 3) * 2;
    const int warp_m = wid & 1;      // e: 2 x 64
    const int warp_n = wid >> 1;     // d: 4 x 32

    const int z = blockIdx.z;
    const int bh = z >> 6, c = z & 63;
    const int hd = bh & 3;
    const int e0 = blockIdx.x * 128;
    const int d0 = blockIdx.y * 128;
    const float gamma = 1.0f - exp2f(-(float)(5 + hd));
    if (tid < 64) gj[tid] = powf(gamma, (float)(63 - tid));
    __syncthreads();

    const float* kptr = K + ((size_t)bh * NSEQ + c * 64) * DK;
    const float* vptr = V + ((size_t)bh * NSEQ + c * 64) * DV;

    // transposed loads: j = tid>>2, 32 cols each
    {
        const int j = tid >> 2;
        const int c0 = (tid & 3) * 32;
        const float sk = gj[j];
        #pragma unroll
        for (int u = 0; u < 8; u++) {
            float4 vv = *(const float4*)(vptr + (size_t)j * DV + e0 + c0 + u * 4);
            const float va[4] = {vv.x, vv.y, vv.z, vv.w};
            #pragma unroll
            for (int x = 0; x < 4; x++)
                split_store(vTh, vTl, (c0 + u * 4 + x) * RSTR + j, va[x]);
            float4 kk = *(const float4*)(kptr + (size_t)j * DK + d0 + c0 + u * 4);
            const float ka[4] = {kk.x * sk, kk.y * sk, kk.z * sk, kk.w * sk};
            #pragma unroll
            for (int x = 0; x < 4; x++)
                split_store(kTh, kTl, (c0 + u * 4 + x) * RSTR + j, ka[x]);
        }
    }
    __syncthreads();

    float acc[4][4][4];
    #pragma unroll
    for (int mt = 0; mt < 4; mt++)
        #pragma unroll
        for (int nt = 0; nt < 4; nt++)
            #pragma unroll
            for (int r = 0; r < 4; r++) acc[mt][nt][r] = 0.0f;

    #pragma unroll
    for (int ks = 0; ks < 4; ks++) {
        const int kb = ks * 16;
        uint32_t bh_[4][2], bl_[4][2];
        #pragma unroll
        for (int nt = 0; nt < 4; nt++) {
            const int nrow = warp_n * 32 + nt * 8 + g;
            const int ko = nrow * RSTR + kb + cq;
            bh_[nt][0] = *(const uint32_t*)&kTh[ko];
            bh_[nt][1] = *(const uint32_t*)&kTh[ko + 8];
            bl_[nt][0] = *(const uint32_t*)&kTl[ko];
            bl_[nt][1] = *(const uint32_t*)&kTl[ko + 8];
        }
        #pragma unroll
        for (int mt = 0; mt < 4; mt++) {
            const int mrow = warp_m * 64 + mt * 16 + g;
            const int ao = mrow * RSTR + kb + cq;
            uint32_t ah[4], al[4];
            ah[0] = *(const uint32_t*)&vTh[ao];
            ah[1] = *(const uint32_t*)&vTh[ao + 8 * RSTR];
            ah[2] = *(const uint32_t*)&vTh[ao + 8];
            ah[3] = *(const uint32_t*)&vTh[ao + 8 * RSTR + 8];
            al[0] = *(const uint32_t*)&vTl[ao];
            al[1] = *(const uint32_t*)&vTl[ao + 8 * RSTR];
            al[2] = *(const uint32_t*)&vTl[ao + 8];
            al[3] = *(const uint32_t*)&vTl[ao + 8 * RSTR + 8];
            #pragma unroll
            for (int nt = 0; nt < 4; nt++) {
                mma16816(acc[mt][nt], ah, bh_[nt]);
                mma16816(acc[mt][nt], ah, bl_[nt]);
                mma16816(acc[mt][nt], al, bh_[nt]);
            }
        }
    }

    float* uptr = U + (size_t)z * DK * DV;
    #pragma unroll
    for (int mt = 0; mt < 4; mt++) {
        #pragma unroll
        for (int nt = 0; nt < 4; nt++) {
            const int e = e0 + warp_m * 64 + mt * 16 + g;
            const int d = d0 + warp_n * 32 + nt * 8 + cq;
            #pragma unroll
            for (int half = 0; half < 2; half++) {
                float2* p = (float2*)(uptr + (size_t)(e + half * 8) * DK + d);
                *p = make_float2(acc[mt][nt][half * 2], acc[mt][nt][half * 2 + 1]);
            }
        }
    }
}

// ---------------- phase B: decay scan, emits S as bf16 hi/lo ----------------
__global__ void scan_state(const float* __restrict__ U,
                           __nv_bfloat16* __restrict__ Sh, __nv_bfloat16* __restrict__ Sl)
{
    const int idx = blockIdx.x * blockDim.x + threadIdx.x;   // 8*512*128
    const int d2 = (idx & 127) * 2;
    const int e  = (idx >> 7) & 511;
    const int bh = idx >> 16;
    const int hd = bh & 3;
    const float gamma = 1.0f - exp2f(-(float)(5 + hd));
    const float gC = powf(gamma, 64.0f);
    const size_t base = ((size_t)bh * 64) * (DK * DV) + (size_t)e * DK + d2;
    float s0 = 0.0f, s1 = 0.0f;
    for (int c = 0; c < 64; c++) {
        const size_t off = base + (size_t)c * (DK * DV);
        const __nv_bfloat16 h0 = __float2bfloat16(s0);
        const __nv_bfloat16 h1 = __float2bfloat16(s1);
        *(__nv_bfloat162*)(Sh + off) = __halves2bfloat162(h0, h1);
        *(__nv_bfloat162*)(Sl + off) = __halves2bfloat162(
            __float2bfloat16(s0 - __bfloat162float(h0)),
            __float2bfloat16(s1 - __bfloat162float(h1)));
        const float2 u = *(const float2*)(U + off);
        s0 = gC * s0 + u.x;
        s1 = gC * s1 + u.y;
    }
}

// =====================================================================
//  phase C (mma): o = mask(q k^T) V + (q * gamma^(i+1)) S
//  block: z chunk (y), e-block 128 (x). 256 threads (8 warps).
// =====================================================================
#define RET_BUFA 27648                      // elems: phase buffers
#define RET_DSMEM ((RET_BUFA + 2 * 4608) * 2)

__global__ __launch_bounds__(256)
void retention_mma(const float* __restrict__ Q, const float* __restrict__ Kp,
                   const float* __restrict__ V,
                   const __nv_bfloat16* __restrict__ Sh, const __nv_bfloat16* __restrict__ Sl,
                   float* __restrict__ O)
{
    extern __shared__ __nv_bfloat16 sm[];
    __nv_bfloat16* bufA  = sm;
    __nv_bfloat16* attnh = sm + RET_BUFA;
    __nv_bfloat16* attnl = sm + RET_BUFA + 4608;
    __shared__ float gpow[72];

    const int tid = threadIdx.x;
    const int wid = tid >> 5, lane = tid & 31;
    const int g = lane >> 2, cq = (lane & 3) * 2;

    const int z = blockIdx.y;
    const int bh = z >> 6, c = z & 63;
    const int hd = bh & 3, b = bh >> 2;
    const int e0 = blockIdx.x * 128;
    const float gamma = 1.0f - exp2f(-(float)(5 + hd));
    if (tid < 66) gpow[tid] = powf(gamma, (float)tid);
    __syncthreads();

    const float* qptr = Q + ((size_t)bh * NSEQ + c * 64) * DK;
    const float* kptr = Kp + ((size_t)bh * NSEQ + c * 64) * DK;
    const float* vptr = V + ((size_t)bh * NSEQ + c * 64) * DV;
    const size_t soff = (size_t)z * DK * DV;

    // ---------------- phase 1: attn = q k^T (m64 n64 k256) ----------------
    const int w_i = wid & 1;     // 2 x 32 rows
    const int w_j = wid >> 1;    // 4 x 16 cols
    float acc_a[2][2][4];
    #pragma unroll
    for (int mt = 0; mt < 2; mt++)
        #pragma unroll
        for (int nt = 0; nt < 2; nt++)
            #pragma unroll
            for (int r = 0; r < 4; r++) acc_a[mt][nt][r] = 0.0f;

    __nv_bfloat16* qh = bufA;
    __nv_bfloat16* ql = bufA + 4608;
    __nv_bfloat16* kh = bufA + 9216;
    __nv_bfloat16* kl = bufA + 13824;

    const int lrow = tid >> 2;          // 0..63
    const int lc0  = (tid & 3) * 16;

    for (int dc = 0; dc < 4; dc++) {
        const int dbase = dc * 64;
        #pragma unroll
        for (int u = 0; u < 4; u++) {
            float4 qv = *(const float4*)(qptr + (size_t)lrow * DK + dbase + lc0 + u * 4);
            const float qa[4] = {qv.x, qv.y, qv.z, qv.w};
            #pragma unroll
            for (int x = 0; x < 4; x++)
                split_store(qh, ql, lrow * RSTR + lc0 + u * 4 + x, qa[x]);
            float4 kv = *(const float4*)(kptr + (size_t)lrow * DK + dbase + lc0 + u * 4);
            const float ka[4] = {kv.x, kv.y, kv.z, kv.w};
            #pragma unroll
            for (int x = 0; x < 4; x++)
                split_store(kh, kl, lrow * RSTR + lc0 + u * 4 + x, ka[x]);
        }
        __syncthreads();

        #pragma unroll
        for (int ks = 0; ks < 4; ks++) {
            const int kb = ks * 16;
            uint32_t bh_[2][2], bl_[2][2];
            #pragma unroll
            for (int nt = 0; nt < 2; nt++) {
                const int nrow = w_j * 16 + nt * 8 + g;
                const int ko = nrow * RSTR + kb + cq;
                bh_[nt][0] = *(const uint32_t*)&kh[ko];
                bh_[nt][1] = *(const uint32_t*)&kh[ko + 8];
                bl_[nt][0] = *(const uint32_t*)&kl[ko];
                bl_[nt][1] = *(const uint32_t*)&kl[ko + 8];
            }
            #pragma unroll
            for (int mt = 0; mt < 2; mt++) {
                const int mrow = w_i * 32 + mt * 16 + g;
                const int ao = mrow * RSTR + kb + cq;
                uint32_t ah[4], al[4];
                ah[0] = *(const uint32_t*)&qh[ao];
                ah[1] = *(const uint32_t*)&qh[ao + 8 * RSTR];
                ah[2] = *(const uint32_t*)&qh[ao + 8];
                ah[3] = *(const uint32_t*)&qh[ao + 8 * RSTR + 8];
                al[0] = *(const uint32_t*)&ql[ao];
                al[1] = *(const uint32_t*)&ql[ao + 8 * RSTR];
                al[2] = *(const uint32_t*)&ql[ao + 8];
                al[3] = *(const uint32_t*)&ql[ao + 8 * RSTR + 8];
                #pragma unroll
                for (int nt = 0; nt < 2; nt++) {
                    mma16816(acc_a[mt][nt], ah, bh_[nt]);
                    mma16816(acc_a[mt][nt], ah, bl_[nt]);
                    mma16816(acc_a[mt][nt], al, bh_[nt]);
                }
            }
        }
        __syncthreads();
    }

    // mask + decay, store attn as bf16 split
    #pragma unroll
    for (int mt = 0; mt < 2; mt++)
        #pragma unroll
        for (int nt = 0; nt < 2; nt++)
            #pragma unroll
            for (int half = 0; half < 2; half++) {
                const int i = w_i * 32 + mt * 16 + g + half * 8;
                #pragma unroll
                for (int x = 0; x < 2; x++) {
                    const int j = w_j * 16 + nt * 8 + cq + x;
                    const float v = (i >= j) ? acc_a[mt][nt][half * 2 + x] * gpow[i - j] : 0.0f;
                    split_store(attnh, attnl, i * RSTR + j, v);
                }
            }
    __syncthreads();

    // ---------------- phase 2: o += attn @ V (m64 n128 k64) ----------------
    const int w_i2 = wid & 1;     // 2 x 32 rows
    const int w_e  = wid >> 1;    // 4 x 32 cols
    float acc_o[2][4][4];
    #pragma unroll
    for (int mt = 0; mt < 2; mt++)
        #pragma unroll
        for (int nt = 0; nt < 4; nt++)
            #pragma unroll
            for (int r = 0; r < 4; r++) acc_o[mt][nt][r] = 0.0f;

    __nv_bfloat16* vTh = bufA;
    __nv_bfloat16* vTl = bufA + 9216;
    {
        const int j = tid >> 2;
        const int c0 = (tid & 3) * 32;
        #pragma unroll
        for (int u = 0; u < 8; u++) {
            float4 vv = *(const float4*)(vptr + (size_t)j * DV + e0 + c0 + u * 4);
            const float va[4] = {vv.x, vv.y, vv.z, vv.w};
            #pragma unroll
            for (int x = 0; x < 4; x++)
                split_store(vTh, vTl, (c0 + u * 4 + x) * RSTR + j, va[x]);
        }
    }
    __syncthreads();

    #pragma unroll
    for (int ks = 0; ks < 4; ks++) {
        const int kb = ks * 16;
        uint32_t bh_[4][2], bl_[4][2];
        #pragma unroll
        for (int nt = 0; nt < 4; nt++) {
            const int nrow = w_e * 32 + nt * 8 + g;
            const int ko = nrow * RSTR + kb + cq;
            bh_[nt][0] = *(const uint32_t*)&vTh[ko];
            bh_[nt][1] = *(const uint32_t*)&vTh[ko + 8];
            bl_[nt][0] = *(const uint32_t*)&vTl[ko];
            bl_[nt][1] = *(const uint32_t*)&vTl[ko + 8];
        }
        #pragma unroll
        for (int mt = 0; mt < 2; mt++) {
            const int mrow = w_i2 * 32 + mt * 16 + g;
            const int ao = mrow * RSTR + kb + cq;
            uint32_t ah[4], al[4];
            ah[0] = *(const uint32_t*)&attnh[ao];
            ah[1] = *(const uint32_t*)&attnh[ao + 8 * RSTR];
            ah[2] = *(const uint32_t*)&attnh[ao + 8];
            ah[3] = *(const uint32_t*)&attnh[ao + 8 * RSTR + 8];
            al[0] = *(const uint32_t*)&attnl[ao];
            al[1] = *(const uint32_t*)&attnl[ao + 8 * RSTR];
            al[2] = *(const uint32_t*)&attnl[ao + 8];
            al[3] = *(const uint32_t*)&attnl[ao + 8 * RSTR + 8];
            #pragma unroll
            for (int nt = 0; nt < 4; nt++) {
                mma16816(acc_o[mt][nt], ah, bh_[nt]);
                mma16816(acc_o[mt][nt], ah, bl_[nt]);
                mma16816(acc_o[mt][nt], al, bh_[nt]);
            }
        }
    }
    __syncthreads();

    // ---------------- phase 3: o += (q * gamma^(i+1)) @ S (m64 n128 k256) ----------------
    __nv_bfloat16* qch = bufA;
    __nv_bfloat16* qcl = bufA + 4608;
    __nv_bfloat16* sth = bufA + 9216;
    __nv_bfloat16* stl = bufA + 18432;

    for (int dc = 0; dc < 4; dc++) {
        const int dbase = dc * 64;
        // qc load (row = i)
        {
            const float sc = gpow[lrow + 1];
            #pragma unroll
            for (int u = 0; u < 4; u++) {
                float4 qv = *(const float4*)(qptr + (size_t)lrow * DK + dbase + lc0 + u * 4);
                const float qa[4] = {qv.x * sc, qv.y * sc, qv.z * sc, qv.w * sc};
                #pragma unroll
                for (int x = 0; x < 4; x++)
                    split_store(qch, qcl, lrow * RSTR + lc0 + u * 4 + x, qa[x]);
            }
        }
        // St tiles: rows e (128), cols d (64), natural layout — direct uint4 copies
        {
            const int e = tid >> 1;
            const int c0 = (tid & 1) * 32;
            const size_t gsrc = soff + (size_t)(e0 + e) * DK + dbase + c0;
            #pragma unroll
            for (int u = 0; u < 4; u++) {
                *(uint4*)&sth[e * RSTR + c0 + u * 8] = *(const uint4*)(Sh + gsrc + u * 8);
                *(uint4*)&stl[e * RSTR + c0 + u * 8] = *(const uint4*)(Sl + gsrc + u * 8);
            }
        }
        __syncthreads();

        #pragma unroll
        for (int ks = 0; ks < 4; ks++) {
            const int kb = ks * 16;
            uint32_t bh_[4][2], bl_[4][2];
            #pragma unroll
            for (int nt = 0; nt < 4; nt++) {
                const int nrow = w_e * 32 + nt * 8 + g;
                const int ko = nrow * RSTR + kb + cq;
                bh_[nt][0] = *(const uint32_t*)&sth[ko];
                bh_[nt][1] = *(const uint32_t*)&sth[ko + 8];
                bl_[nt][0] = *(const uint32_t*)&stl[ko];
                bl_[nt][1] = *(const uint32_t*)&stl[ko + 8];
            }
            #pragma unroll
            for (int mt = 0; mt < 2; mt++) {
                const int mrow = w_i2 * 32 + mt * 16 + g;
                const int ao = mrow * RSTR + kb + cq;
                uint32_t ah[4], al[4];
                ah[0] = *(const uint32_t*)&qch[ao];
                ah[1] = *(const uint32_t*)&qch[ao + 8 * RSTR];
                ah[2] = *(const uint32_t*)&qch[ao + 8];
                ah[3] = *(const uint32_t*)&qch[ao + 8 * RSTR + 8];
                al[0] = *(const uint32_t*)&qcl[ao];
                al[1] = *(const uint32_t*)&qcl[ao + 8 * RSTR];
                al[2] = *(const uint32_t*)&qcl[ao + 8];
                al[3] = *(const uint32_t*)&qcl[ao + 8 * RSTR + 8];
                #pragma unroll
                for (int nt = 0; nt < 4; nt++) {
                    mma16816(acc_o[mt][nt], ah, bh_[nt]);
                    mma16816(acc_o[mt][nt], ah, bl_[nt]);
                    mma16816(acc_o[mt][nt], al, bh_[nt]);
                }
            }
        }
        __syncthreads();
    }

    // epilogue: O in (B,N,H,dv)
    #pragma unroll
    for (int mt = 0; mt < 2; mt++)
        #pragma unroll
        for (int nt = 0; nt < 4; nt++)
            #pragma unroll
            for (int half = 0; half < 2; half++) {
                const int i = w_i2 * 32 + mt * 16 + g + half * 8;
                const int e = e0 + w_e * 32 + nt * 8 + cq;
                float2* p = (float2*)(O + (((size_t)(b * NSEQ + c * 64 + i)) * H_ + hd) * DV + e);
                *p = make_float2(acc_o[mt][nt][half * 2], acc_o[mt][nt][half * 2 + 1]);
            }
}

// ---------------- rmsnorm * silu-gate -> bf16 hi/lo for Wo GEMM ----------------
__global__ void norm_gate(const float* __restrict__ O, const float* __restrict__ G,
                          const float* __restrict__ w,
                          __nv_bfloat16* __restrict__ Gh, __nv_bfloat16* __restrict__ Gl)
{
    __shared__ float red[4];
    const int row = blockIdx.x;
    const int tid = threadIdx.x;
    const size_t base = (size_t)row * DV;

    float4 x = *(const float4*)(O + base + tid * 4);
    float ss = x.x * x.x + x.y * x.y + x.z * x.z + x.w * x.w;
    #pragma unroll
    for (int off = 16; off; off >>= 1) ss += __shfl_xor_sync(0xffffffff, ss, off);
    if ((tid & 31) == 0) red[tid >> 5] = ss;
    __syncthreads();
    const float tot = red[0] + red[1] + red[2] + red[3];
    const float inv = rsqrtf(tot * (1.0f / (float)DV) + 1e-5f);

    float4 wv = *(const float4*)(w + tid * 4);
    float4 gv = *(const float4*)(G + base + tid * 4);
    float o0 = x.x * inv * wv.x * gv.x;
    float o1 = x.y * inv * wv.y * gv.y;
    float o2 = x.z * inv * wv.z * gv.z;
    float o3 = x.w * inv * wv.w * gv.w;

    const __nv_bfloat16 h0 = __float2bfloat16(o0);
    const __nv_bfloat16 h1 = __float2bfloat16(o1);
    const __nv_bfloat16 h2 = __float2bfloat16(o2);
    const __nv_bfloat16 h3 = __float2bfloat16(o3);
    const size_t p = (base >> 1) + tid * 2;
    ((__nv_bfloat162*)Gh)[p + 0] = __halves2bfloat162(h0, h1);
    ((__nv_bfloat162*)Gh)[p + 1] = __halves2bfloat162(h2, h3);
    ((__nv_bfloat162*)Gl)[p + 0] = __halves2bfloat162(
        __float2bfloat16(o0 - __bfloat162float(h0)), __float2bfloat16(o1 - __bfloat162float(h1)));
    ((__nv_bfloat162*)Gl)[p + 1] = __halves2bfloat162(
        __float2bfloat16(o2 - __bfloat162float(h2)), __float2bfloat16(o3 - __bfloat162float(h3)));
}

// ---------------- launch ----------------
extern "C" void kernel_launch(void* const* d_in, const int* in_sizes, int n_in,
                              void* d_out, int out_size)
{
    const float* x  = (const float*)d_in[0];
    const float* Wq = (const float*)d_in[1];
    const float* Wk = (const float*)d_in[2];
    const float* Wv = (const float*)d_in[3];
    const float* Wg = (const float*)d_in[4];
    const float* Wo = (const float*)d_in[5];
    const float* gw = (const float*)d_in[6];
    float* out = (float*)d_out;

    float *q1, *k1, *q, *k, *v, *g, *o, *U, *S, *ct, *st;
    __nv_bfloat16 *xh, *xl, *wth, *wtl, *gh, *gl;
    cudaGetSymbolAddress((void**)&q1, g_q1);
    cudaGetSymbolAddress((void**)&k1, g_k1);
    cudaGetSymbolAddress((void**)&q,  g_q);
    cudaGetSymbolAddress((void**)&k,  g_k);
    cudaGetSymbolAddress((void**)&v,  g_v);
    cudaGetSymbolAddress((void**)&g,  g_g);
    cudaGetSymbolAddress((void**)&o,  g_o);
    cudaGetSymbolAddress((void**)&U,  g_U);
    cudaGetSymbolAddress((void**)&S,  g_S);
    cudaGetSymbolAddress((void**)&ct, g_cos);
    cudaGetSymbolAddress((void**)&st, g_sin);
    cudaGetSymbolAddress((void**)&xh, g_xh);
    cudaGetSymbolAddress((void**)&xl, g_xl);
    cudaGetSymbolAddress((void**)&wth, g_wth);
    cudaGetSymbolAddress((void**)&wtl, g_wtl);
    cudaGetSymbolAddress((void**)&gh, g_gh);
    cudaGetSymbolAddress((void**)&gl, g_gl);

    __nv_bfloat16* Sh = (__nv_bfloat16*)S;
    __nv_bfloat16* Sl = Sh + SELEMS;

    cudaFuncSetAttribute(gemm_mma<0>, cudaFuncAttributeMaxDynamicSharedMemorySize, GEMM_DSMEM);
    cudaFuncSetAttribute(gemm_mma<1>, cudaFuncAttributeMaxDynamicSharedMemorySize, GEMM_DSMEM);
    cudaFuncSetAttribute(gemm_mma<2>, cudaFuncAttributeMaxDynamicSharedMemorySize, GEMM_DSMEM);
    cudaFuncSetAttribute(chunk_kv_mma, cudaFuncAttributeMaxDynamicSharedMemorySize, CKV_DSMEM);
    cudaFuncSetAttribute(retention_mma, cudaFuncAttributeMaxDynamicSharedMemorySize, RET_DSMEM);

    const int M = B_ * NSEQ;  // 8192

    // bf16 splits: activations + transposed weights
    split_rows<<<(M * DM / 4) / 256, 256>>>(x, xh, xl);
    wsplitT<<<dim3(DM / 32, DM / 32), dim3(32, 8)>>>(Wq, wth + WOFF_Q, wtl + WOFF_Q, DM, DM);
    wsplitT<<<dim3(DM / 32, DM / 32), dim3(32, 8)>>>(Wk, wth + WOFF_K, wtl + WOFF_K, DM, DM);
    wsplitT<<<dim3(VD / 32, DM / 32), dim3(32, 8)>>>(Wv, wth + WOFF_V, wtl + WOFF_V, DM, VD);
    wsplitT<<<dim3(VD / 32, DM / 32), dim3(32, 8)>>>(Wg, wth + WOFF_G, wtl + WOFF_G, DM, VD);
    wsplitT<<<dim3(DM / 32, VD / 32), dim3(32, 8)>>>(Wo, wth + WOFF_O, wtl + WOFF_O, VD, DM);

    // tensor-pipe projections
    gemm_mma<0><<<dim3(DM / BN, M / BM), 256, GEMM_DSMEM>>>(xh, xl, wth + WOFF_Q, wtl + WOFF_Q, q1, M, DM, DM);
    gemm_mma<0><<<dim3(DM / BN, M / BM), 256, GEMM_DSMEM>>>(xh, xl, wth + WOFF_K, wtl + WOFF_K, k1, M, DM, DM);
    gemm_mma<2><<<dim3(VD / BN, M / BM), 256, GEMM_DSMEM>>>(xh, xl, wth + WOFF_V, wtl + WOFF_V, v, M, VD, DM);
    gemm_mma<1><<<dim3(VD / BN, M / BM), 256, GEMM_DSMEM>>>(xh, xl, wth + WOFF_G, wtl + WOFF_G, g, M, VD, DM);

    // rotary
    rope_table<<<NSEQ, 128>>>(ct, st);
    rope_apply<<<(B_ * NSEQ * H_ * 128) / 256, 256>>>(q1, k1, q, k, ct, st);

    // retention on tensor pipe
    chunk_kv_mma<<<dim3(DV / 128, DK / 128, B_ * H_ * NC), 256, CKV_DSMEM>>>(k, v, U);
    scan_state<<<(B_ * H_ * DV * (DK / 2)) / 256, 256>>>(U, Sh, Sl);
    retention_mma<<<dim3(DV / 128, B_ * H_ * NC), 256, RET_DSMEM>>>(q, k, v, Sh, Sl, o);

    // rmsnorm + gate, then output projection
    norm_gate<<<B_ * NSEQ * H_, 128>>>(o, g, gw, gh, gl);
    gemm_mma<0><<<dim3(DM / BN, M / BM), 256, GEMM_DSMEM>>>(gh, gl, wth + WOFF_O, wtl + WOFF_O, out, M, DM, VD);
}